// round 1
// baseline (speedup 1.0000x reference)
#include <cuda_runtime.h>
#include <cuda_bf16.h>
#include <cstdint>
#include <cstddef>

// Problem constants
#define B_ 4
#define S_ 2048
#define D_ 1024
#define H_ 16
#define DH_ 64
#define M_ (B_ * S_)      // 8192
#define N_QKV (3 * D_)    // 3072

// Scratch (device globals — no allocation allowed)
__device__ float g_q[(size_t)B_ * H_ * S_ * DH_];   // [B,H,S,Dh], pre-scaled by 1/8
__device__ float g_k[(size_t)B_ * H_ * S_ * DH_];
__device__ float g_v[(size_t)B_ * H_ * S_ * DH_];
__device__ float g_ctx[(size_t)M_ * D_];            // [B,S,D]

// ---------------------------------------------------------------------------
// SGEMM: C[m,n] = sum_k A[m,k] * W[n,k] + bias[n]
// A: [M,K] row-major, W: [N,K] row-major. 128x128 tile, BK=8, 8x8 per thread.
// EPI = 0: plain store to C.  EPI = 1: scatter into g_q/g_k/g_v.
// ---------------------------------------------------------------------------
template <int EPI>
__global__ __launch_bounds__(256) void sgemm_kernel(
    const float* __restrict__ A, const float* __restrict__ W,
    const float* __restrict__ bias, float* __restrict__ C,
    int N, int K)
{
    __shared__ float As[8][128];
    __shared__ float Ws[8][128];

    const int tid = threadIdx.x;
    const int bm = blockIdx.y * 128;
    const int bn = blockIdx.x * 128;

    const int lrow = tid >> 1;        // 0..127
    const int lk   = (tid & 1) << 2;  // 0 or 4

    const float* Ap = A + (size_t)(bm + lrow) * K + lk;
    const float* Wp = W + (size_t)(bn + lrow) * K + lk;

    float acc[8][8];
#pragma unroll
    for (int i = 0; i < 8; i++)
#pragma unroll
        for (int j = 0; j < 8; j++) acc[i][j] = 0.0f;

    const int tm = (tid >> 4) << 3;  // 0..120 step 8
    const int tn = (tid & 15) << 3;

    for (int k0 = 0; k0 < K; k0 += 8) {
        float4 av = *(const float4*)(Ap + k0);
        float4 wv = *(const float4*)(Wp + k0);
        As[lk + 0][lrow] = av.x; As[lk + 1][lrow] = av.y;
        As[lk + 2][lrow] = av.z; As[lk + 3][lrow] = av.w;
        Ws[lk + 0][lrow] = wv.x; Ws[lk + 1][lrow] = wv.y;
        Ws[lk + 2][lrow] = wv.z; Ws[lk + 3][lrow] = wv.w;
        __syncthreads();

#pragma unroll
        for (int kk = 0; kk < 8; kk++) {
            float a[8], b[8];
            *(float4*)(a)     = *(const float4*)&As[kk][tm];
            *(float4*)(a + 4) = *(const float4*)&As[kk][tm + 4];
            *(float4*)(b)     = *(const float4*)&Ws[kk][tn];
            *(float4*)(b + 4) = *(const float4*)&Ws[kk][tn + 4];
#pragma unroll
            for (int i = 0; i < 8; i++)
#pragma unroll
                for (int j = 0; j < 8; j++)
                    acc[i][j] = fmaf(a[i], b[j], acc[i][j]);
        }
        __syncthreads();
    }

    if (EPI == 0) {
        // plain: C[m*N + n]
#pragma unroll
        for (int i = 0; i < 8; i++) {
            const int m = bm + tm + i;
#pragma unroll
            for (int j = 0; j < 8; j++) {
                const int n = bn + tn + j;
                C[(size_t)m * N + n] = acc[i][j] + bias[n];
            }
        }
    } else {
        // scatter into Q/K/V head-major [B,H,S,Dh]; Q pre-scaled by 1/8
#pragma unroll
        for (int i = 0; i < 8; i++) {
            const int m = bm + tm + i;
            const int b = m >> 11;        // /2048
            const int s = m & 2047;
#pragma unroll
            for (int j = 0; j < 8; j++) {
                const int n = bn + tn + j;
                float v = acc[i][j] + bias[n];
                const int c = n >> 10;    // 0=q,1=k,2=v
                const int r = n & 1023;
                const int h = r >> 6;
                const int d = r & 63;
                const size_t idx = (((size_t)(b * H_ + h)) * S_ + s) * DH_ + d;
                if (c == 0)      g_q[idx] = v * 0.125f;
                else if (c == 1) g_k[idx] = v;
                else             g_v[idx] = v;
            }
        }
    }
}

// ---------------------------------------------------------------------------
// Causal flash attention, fp32. Grid: (S/64, B*H). Block: 256 (16x16).
// 64x64 Q tile per CTA, streams 64-row K/V tiles. P reuses the K smem buffer.
// Dynamic smem: 3 * 64 * 65 floats = 49,920 B.
// ---------------------------------------------------------------------------
#define LDSTR 65

__global__ __launch_bounds__(256) void attn_kernel(float* __restrict__ ctx)
{
    extern __shared__ float sm[];
    float* Qs = sm;                  // [64][65]
    float* Ks = sm + 64 * LDSTR;     // [64][65], reused as P
    float* Vs = sm + 2 * 64 * LDSTR; // [64][65]

    const int qb = blockIdx.x;       // 0..31
    const int bh = blockIdx.y;       // 0..63 (b*16+h)
    const int b  = bh >> 4;
    const int h  = bh & 15;
    const size_t base = (size_t)bh * (S_ * DH_);
    const int q0 = qb * 64;

    const int tid = threadIdx.x;
    const int tx = tid & 15;         // col group
    const int ty = tid >> 4;         // row group
    const int r0 = ty * 4;
    const int c0 = tx * 4;

    // Load Q tile (64x64) as float4, transposed-free (row,dim)
    for (int i = tid; i < 64 * 16; i += 256) {
        const int r = i >> 4;
        const int c = (i & 15) << 2;
        float4 v = *(const float4*)(g_q + base + (size_t)(q0 + r) * DH_ + c);
        Qs[r * LDSTR + c + 0] = v.x; Qs[r * LDSTR + c + 1] = v.y;
        Qs[r * LDSTR + c + 2] = v.z; Qs[r * LDSTR + c + 3] = v.w;
    }

    float m_i[4], l_i[4], o[4][4];
#pragma unroll
    for (int i = 0; i < 4; i++) {
        m_i[i] = -1e30f; l_i[i] = 0.0f;
#pragma unroll
        for (int j = 0; j < 4; j++) o[i][j] = 0.0f;
    }
    __syncthreads();

    for (int kb = 0; kb <= qb; kb++) {
        // Load K,V tiles
        for (int i = tid; i < 64 * 16; i += 256) {
            const int r = i >> 4;
            const int c = (i & 15) << 2;
            const size_t gidx = base + (size_t)(kb * 64 + r) * DH_ + c;
            float4 kv = *(const float4*)(g_k + gidx);
            float4 vv = *(const float4*)(g_v + gidx);
            Ks[r * LDSTR + c + 0] = kv.x; Ks[r * LDSTR + c + 1] = kv.y;
            Ks[r * LDSTR + c + 2] = kv.z; Ks[r * LDSTR + c + 3] = kv.w;
            Vs[r * LDSTR + c + 0] = vv.x; Vs[r * LDSTR + c + 1] = vv.y;
            Vs[r * LDSTR + c + 2] = vv.z; Vs[r * LDSTR + c + 3] = vv.w;
        }
        __syncthreads();

        // S = Q K^T (Q already scaled)
        float s[4][4];
#pragma unroll
        for (int i = 0; i < 4; i++)
#pragma unroll
            for (int j = 0; j < 4; j++) s[i][j] = 0.0f;

#pragma unroll 8
        for (int k = 0; k < 64; k++) {
            float qv[4], kv[4];
#pragma unroll
            for (int i = 0; i < 4; i++) qv[i] = Qs[(r0 + i) * LDSTR + k];
#pragma unroll
            for (int j = 0; j < 4; j++) kv[j] = Ks[(c0 + j) * LDSTR + k];
#pragma unroll
            for (int i = 0; i < 4; i++)
#pragma unroll
                for (int j = 0; j < 4; j++)
                    s[i][j] = fmaf(qv[i], kv[j], s[i][j]);
        }

        // Causal mask on diagonal block
        if (kb == qb) {
#pragma unroll
            for (int i = 0; i < 4; i++)
#pragma unroll
                for (int j = 0; j < 4; j++)
                    if (c0 + j > r0 + i) s[i][j] = -1e30f;
        }

        // Row max (reduce across 16 tx lanes)
        float mnew[4];
#pragma unroll
        for (int i = 0; i < 4; i++) {
            float m = s[i][0];
            m = fmaxf(m, s[i][1]); m = fmaxf(m, s[i][2]); m = fmaxf(m, s[i][3]);
#pragma unroll
            for (int off = 8; off > 0; off >>= 1)
                m = fmaxf(m, __shfl_xor_sync(0xffffffffu, m, off));
            mnew[i] = m;
        }

        float p[4][4], scale[4], rsum[4];
#pragma unroll
        for (int i = 0; i < 4; i++) {
            const float mn = fmaxf(m_i[i], mnew[i]);
            scale[i] = __expf(m_i[i] - mn);
            m_i[i] = mn;
            float rs = 0.0f;
#pragma unroll
            for (int j = 0; j < 4; j++) {
                p[i][j] = __expf(s[i][j] - mn);
                rs += p[i][j];
            }
#pragma unroll
            for (int off = 8; off > 0; off >>= 1)
                rs += __shfl_xor_sync(0xffffffffu, rs, off);
            rsum[i] = rs;
        }
#pragma unroll
        for (int i = 0; i < 4; i++) {
            l_i[i] = l_i[i] * scale[i] + rsum[i];
#pragma unroll
            for (int j = 0; j < 4; j++) o[i][j] *= scale[i];
        }

        __syncthreads();  // everyone done reading Ks
        // Write P into Ks buffer: P[row][col]
#pragma unroll
        for (int i = 0; i < 4; i++)
#pragma unroll
            for (int j = 0; j < 4; j++)
                Ks[(r0 + i) * LDSTR + (c0 + j)] = p[i][j];
        __syncthreads();

        // O += P @ V  (o[i][j]: row r0+i, dim c0+j)
#pragma unroll 8
        for (int k = 0; k < 64; k++) {
            float pr[4], vc[4];
#pragma unroll
            for (int i = 0; i < 4; i++) pr[i] = Ks[(r0 + i) * LDSTR + k];
#pragma unroll
            for (int j = 0; j < 4; j++) vc[j] = Vs[k * LDSTR + (c0 + j)];
#pragma unroll
            for (int i = 0; i < 4; i++)
#pragma unroll
                for (int j = 0; j < 4; j++)
                    o[i][j] = fmaf(pr[i], vc[j], o[i][j]);
        }
        __syncthreads();  // before next tile overwrites Ks/Vs
    }

    // Epilogue: ctx[b][s][h*64+d]
#pragma unroll
    for (int i = 0; i < 4; i++) {
        const float inv = 1.0f / l_i[i];
        const size_t row = (size_t)(b * S_ + q0 + r0 + i) * D_ + h * DH_ + c0;
#pragma unroll
        for (int j = 0; j < 4; j++)
            ctx[row + j] = o[i][j] * inv;
    }
}

// ---------------------------------------------------------------------------
extern "C" void kernel_launch(void* const* d_in, const int* in_sizes, int n_in,
                              void* d_out, int out_size)
{
    const float* x     = (const float*)d_in[0];
    // d_in[1] = mask (causal, implied) — unused
    const float* w_qkv = (const float*)d_in[2];
    const float* b_qkv = (const float*)d_in[3];
    const float* w_out = (const float*)d_in[4];
    const float* b_out = (const float*)d_in[5];
    float* out = (float*)d_out;

    float* ctx_ptr = nullptr;
    cudaGetSymbolAddress((void**)&ctx_ptr, g_ctx);

    // 1) QKV projection with scatter epilogue
    {
        dim3 grid(N_QKV / 128, M_ / 128);
        sgemm_kernel<1><<<grid, 256>>>(x, w_qkv, b_qkv, nullptr, N_QKV, D_);
    }

    // 2) Causal attention
    {
        const int smem = 3 * 64 * LDSTR * (int)sizeof(float); // 49,920 B
        cudaFuncSetAttribute(attn_kernel,
                             cudaFuncAttributeMaxDynamicSharedMemorySize, smem);
        dim3 grid(S_ / 64, B_ * H_);
        attn_kernel<<<grid, 256, smem>>>(ctx_ptr);
    }

    // 3) Output projection
    {
        dim3 grid(D_ / 128, M_ / 128);
        sgemm_kernel<0><<<grid, 256>>>(ctx_ptr, w_out, b_out, out, D_, D_);
    }
}

// round 4
// speedup vs baseline: 1.6398x; 1.6398x over previous
#include <cuda_runtime.h>
#include <cstdint>
#include <cstddef>

// Problem constants
#define B_ 4
#define S_ 2048
#define D_ 1024
#define H_ 16
#define DH_ 64
#define M_ (B_ * S_)      // 8192
#define N_QKV (3 * D_)    // 3072

// Scratch (device globals — no allocation allowed)
__device__ float g_q[(size_t)B_ * H_ * S_ * DH_];   // [B,H,S,Dh], pre-scaled by 1/8
__device__ float g_k[(size_t)B_ * H_ * S_ * DH_];
__device__ float g_v[(size_t)B_ * H_ * S_ * DH_];
__device__ float g_ctx[(size_t)M_ * D_];            // [B,S,D]

// ---------------------------------------------------------------------------
// mma.sync tf32 helpers (baseline PTX — works on compute_103 base target)
// ---------------------------------------------------------------------------
__device__ __forceinline__ uint32_t f2tf32(float f) {
    uint32_t r;
    asm("cvt.rna.tf32.f32 %0, %1;" : "=r"(r) : "f"(f));
    return r;
}

__device__ __forceinline__ void mma_tf32(float* c, const uint32_t* a,
                                         const uint32_t* b) {
    asm volatile(
        "mma.sync.aligned.m16n8k8.row.col.f32.tf32.tf32.f32 "
        "{%0,%1,%2,%3}, {%4,%5,%6,%7}, {%8,%9}, {%0,%1,%2,%3};"
        : "+f"(c[0]), "+f"(c[1]), "+f"(c[2]), "+f"(c[3])
        : "r"(a[0]), "r"(a[1]), "r"(a[2]), "r"(a[3]), "r"(b[0]), "r"(b[1]));
}

// swizzled float index within a 128x32-float tile (128B rows, xor swizzle)
__device__ __forceinline__ int swz_idx(int r, int c4) {
    return r * 32 + ((c4 ^ (r & 7)) << 2);
}

// ---------------------------------------------------------------------------
// Tensor-core GEMM: C[m,n] = sum_k A[m,k] * W[n,k] + bias[n]
// A:[M,K] row-major, W:[N,K] row-major. Tile 128x128, BK=32.
// 8 warps (2m x 4n), warp tile 64x32, m16n8k8 tf32 MMA.
// Smem rows are 32 floats (128B) with SW128-style xor swizzle.
// EPI=0: plain store.  EPI=1: scatter to g_q/g_k/g_v (Q scaled 1/8).
// ---------------------------------------------------------------------------
template <int EPI>
__global__ __launch_bounds__(256) void mma_gemm(
    const float* __restrict__ A, const float* __restrict__ W,
    const float* __restrict__ bias, float* __restrict__ C,
    int N, int K)
{
    __shared__ uint32_t As[128 * 32];
    __shared__ uint32_t Bs[128 * 32];

    const int tid = threadIdx.x;
    const int wid = tid >> 5;
    const int lane = tid & 31;
    const int g = lane >> 2;      // group 0..7
    const int t = lane & 3;       // thread-in-group
    const int wm = wid >> 2;      // 0..1
    const int wn = wid & 3;       // 0..3
    const int m0 = wm * 64;
    const int n0 = wn * 32;

    const int bm = blockIdx.y * 128;
    const int bn = blockIdx.x * 128;

    const float* Ag = A + (size_t)bm * K;
    const float* Wg = W + (size_t)bn * K;

    // loader: 1024 float4 per tile per chunk; thread does 4 (rows lr+32q)
    const int lr  = tid >> 3;     // 0..31
    const int lc4 = tid & 7;      // float4 column in 128B row

    float c[4][4][4];
#pragma unroll
    for (int i = 0; i < 4; i++)
#pragma unroll
        for (int j = 0; j < 4; j++)
#pragma unroll
            for (int q = 0; q < 4; q++) c[i][j][q] = 0.0f;

    float4 av[4], wv[4];

    // preload chunk 0
#pragma unroll
    for (int q = 0; q < 4; q++) {
        const int r = lr + 32 * q;
        av[q] = *(const float4*)(Ag + (size_t)r * K + lc4 * 4);
        wv[q] = *(const float4*)(Wg + (size_t)r * K + lc4 * 4);
    }
#pragma unroll
    for (int q = 0; q < 4; q++) {
        const int r = lr + 32 * q;
        const int off = swz_idx(r, lc4);
        As[off + 0] = f2tf32(av[q].x); As[off + 1] = f2tf32(av[q].y);
        As[off + 2] = f2tf32(av[q].z); As[off + 3] = f2tf32(av[q].w);
        Bs[off + 0] = f2tf32(wv[q].x); Bs[off + 1] = f2tf32(wv[q].y);
        Bs[off + 2] = f2tf32(wv[q].z); Bs[off + 3] = f2tf32(wv[q].w);
    }
    __syncthreads();

    const int NCH = K >> 5;   // 32
    for (int ch = 0; ch < NCH; ch++) {
        if (ch + 1 < NCH) {
            const int kc = (ch + 1) * 32;
#pragma unroll
            for (int q = 0; q < 4; q++) {
                const int r = lr + 32 * q;
                av[q] = *(const float4*)(Ag + (size_t)r * K + kc + lc4 * 4);
                wv[q] = *(const float4*)(Wg + (size_t)r * K + kc + lc4 * 4);
            }
        }

        // compute on current smem tile
#pragma unroll
        for (int ks = 0; ks < 4; ks++) {
            const int kc = ks * 8;
            uint32_t afr[4][4];
#pragma unroll
            for (int mt = 0; mt < 4; mt++) {
                const int r = m0 + mt * 16 + g;
                const int r8 = r + 8;
                afr[mt][0] = As[r * 32 + ((((kc + t) >> 2) ^ (r & 7)) << 2) + (t & 3)];
                afr[mt][1] = As[r8 * 32 + ((((kc + t) >> 2) ^ (r8 & 7)) << 2) + (t & 3)];
                afr[mt][2] = As[r * 32 + ((((kc + 4 + t) >> 2) ^ (r & 7)) << 2) + (t & 3)];
                afr[mt][3] = As[r8 * 32 + ((((kc + 4 + t) >> 2) ^ (r8 & 7)) << 2) + (t & 3)];
            }
            uint32_t bfr[4][2];
#pragma unroll
            for (int nt = 0; nt < 4; nt++) {
                const int r = n0 + nt * 8 + g;
                bfr[nt][0] = Bs[r * 32 + ((((kc + t) >> 2) ^ (r & 7)) << 2) + (t & 3)];
                bfr[nt][1] = Bs[r * 32 + ((((kc + 4 + t) >> 2) ^ (r & 7)) << 2) + (t & 3)];
            }
#pragma unroll
            for (int mt = 0; mt < 4; mt++)
#pragma unroll
                for (int nt = 0; nt < 4; nt++)
                    mma_tf32(c[mt][nt], afr[mt], bfr[nt]);
        }
        __syncthreads();

        if (ch + 1 < NCH) {
#pragma unroll
            for (int q = 0; q < 4; q++) {
                const int r = lr + 32 * q;
                const int off = swz_idx(r, lc4);
                As[off + 0] = f2tf32(av[q].x); As[off + 1] = f2tf32(av[q].y);
                As[off + 2] = f2tf32(av[q].z); As[off + 3] = f2tf32(av[q].w);
                Bs[off + 0] = f2tf32(wv[q].x); Bs[off + 1] = f2tf32(wv[q].y);
                Bs[off + 2] = f2tf32(wv[q].z); Bs[off + 3] = f2tf32(wv[q].w);
            }
            __syncthreads();
        }
    }

    // Epilogue. c[mt][nt]: {c0,c1}=(row g, col 2t,2t+1), {c2,c3}=(row g+8, ...)
#pragma unroll
    for (int mt = 0; mt < 4; mt++) {
#pragma unroll
        for (int half = 0; half < 2; half++) {
            const int m = bm + m0 + mt * 16 + g + half * 8;
#pragma unroll
            for (int nt = 0; nt < 4; nt++) {
                const int n = bn + n0 + nt * 8 + t * 2;
                const float v0 = c[mt][nt][half * 2 + 0] + bias[n + 0];
                const float v1 = c[mt][nt][half * 2 + 1] + bias[n + 1];
                if (EPI == 0) {
                    float2 o = make_float2(v0, v1);
                    *(float2*)(C + (size_t)m * N + n) = o;
                } else {
                    const int bb = m >> 11;
                    const int s  = m & 2047;
                    const int cg = n >> 10;     // 0=q,1=k,2=v
                    const int h  = (n & 1023) >> 6;
                    const int d  = n & 63;
                    const float sc = (cg == 0) ? 0.125f : 1.0f;
                    float* dst = (cg == 0) ? g_q : ((cg == 1) ? g_k : g_v);
                    float2 o = make_float2(v0 * sc, v1 * sc);
                    *(float2*)(dst + (((size_t)(bb * H_ + h)) * S_ + s) * DH_ + d) = o;
                }
            }
        }
    }
}

// ---------------------------------------------------------------------------
// Causal flash attention, fp32 SIMT (unchanged, known-good).
// Grid: (S/64, B*H). Block: 256. Dynamic smem: 3*64*65*4 = 49,920 B.
// ---------------------------------------------------------------------------
#define LDSTR 65

__global__ __launch_bounds__(256) void attn_kernel(float* __restrict__ ctx)
{
    extern __shared__ float sm[];
    float* Qs = sm;                  // [64][65]
    float* Ks = sm + 64 * LDSTR;     // [64][65], reused as P
    float* Vs = sm + 2 * 64 * LDSTR; // [64][65]

    const int qb = blockIdx.x;
    const int bh = blockIdx.y;
    const int b  = bh >> 4;
    const int h  = bh & 15;
    const size_t base = (size_t)bh * (S_ * DH_);
    const int q0 = qb * 64;

    const int tid = threadIdx.x;
    const int tx = tid & 15;
    const int ty = tid >> 4;
    const int r0 = ty * 4;
    const int c0 = tx * 4;

    for (int i = tid; i < 64 * 16; i += 256) {
        const int r = i >> 4;
        const int c = (i & 15) << 2;
        float4 v = *(const float4*)(g_q + base + (size_t)(q0 + r) * DH_ + c);
        Qs[r * LDSTR + c + 0] = v.x; Qs[r * LDSTR + c + 1] = v.y;
        Qs[r * LDSTR + c + 2] = v.z; Qs[r * LDSTR + c + 3] = v.w;
    }

    float m_i[4], l_i[4], o[4][4];
#pragma unroll
    for (int i = 0; i < 4; i++) {
        m_i[i] = -1e30f; l_i[i] = 0.0f;
#pragma unroll
        for (int j = 0; j < 4; j++) o[i][j] = 0.0f;
    }
    __syncthreads();

    for (int kb = 0; kb <= qb; kb++) {
        for (int i = tid; i < 64 * 16; i += 256) {
            const int r = i >> 4;
            const int c = (i & 15) << 2;
            const size_t gidx = base + (size_t)(kb * 64 + r) * DH_ + c;
            float4 kv = *(const float4*)(g_k + gidx);
            float4 vv = *(const float4*)(g_v + gidx);
            Ks[r * LDSTR + c + 0] = kv.x; Ks[r * LDSTR + c + 1] = kv.y;
            Ks[r * LDSTR + c + 2] = kv.z; Ks[r * LDSTR + c + 3] = kv.w;
            Vs[r * LDSTR + c + 0] = vv.x; Vs[r * LDSTR + c + 1] = vv.y;
            Vs[r * LDSTR + c + 2] = vv.z; Vs[r * LDSTR + c + 3] = vv.w;
        }
        __syncthreads();

        float s[4][4];
#pragma unroll
        for (int i = 0; i < 4; i++)
#pragma unroll
            for (int j = 0; j < 4; j++) s[i][j] = 0.0f;

#pragma unroll 8
        for (int k = 0; k < 64; k++) {
            float qv[4], kv[4];
#pragma unroll
            for (int i = 0; i < 4; i++) qv[i] = Qs[(r0 + i) * LDSTR + k];
#pragma unroll
            for (int j = 0; j < 4; j++) kv[j] = Ks[(c0 + j) * LDSTR + k];
#pragma unroll
            for (int i = 0; i < 4; i++)
#pragma unroll
                for (int j = 0; j < 4; j++)
                    s[i][j] = fmaf(qv[i], kv[j], s[i][j]);
        }

        if (kb == qb) {
#pragma unroll
            for (int i = 0; i < 4; i++)
#pragma unroll
                for (int j = 0; j < 4; j++)
                    if (c0 + j > r0 + i) s[i][j] = -1e30f;
        }

        float mnew[4];
#pragma unroll
        for (int i = 0; i < 4; i++) {
            float m = s[i][0];
            m = fmaxf(m, s[i][1]); m = fmaxf(m, s[i][2]); m = fmaxf(m, s[i][3]);
#pragma unroll
            for (int off = 8; off > 0; off >>= 1)
                m = fmaxf(m, __shfl_xor_sync(0xffffffffu, m, off));
            mnew[i] = m;
        }

        float p[4][4], scale[4], rsum[4];
#pragma unroll
        for (int i = 0; i < 4; i++) {
            const float mn = fmaxf(m_i[i], mnew[i]);
            scale[i] = __expf(m_i[i] - mn);
            m_i[i] = mn;
            float rs = 0.0f;
#pragma unroll
            for (int j = 0; j < 4; j++) {
                p[i][j] = __expf(s[i][j] - mn);
                rs += p[i][j];
            }
#pragma unroll
            for (int off = 8; off > 0; off >>= 1)
                rs += __shfl_xor_sync(0xffffffffu, rs, off);
            rsum[i] = rs;
        }
#pragma unroll
        for (int i = 0; i < 4; i++) {
            l_i[i] = l_i[i] * scale[i] + rsum[i];
#pragma unroll
            for (int j = 0; j < 4; j++) o[i][j] *= scale[i];
        }

        __syncthreads();
#pragma unroll
        for (int i = 0; i < 4; i++)
#pragma unroll
            for (int j = 0; j < 4; j++)
                Ks[(r0 + i) * LDSTR + (c0 + j)] = p[i][j];
        __syncthreads();

#pragma unroll 8
        for (int k = 0; k < 64; k++) {
            float pr[4], vc[4];
#pragma unroll
            for (int i = 0; i < 4; i++) pr[i] = Ks[(r0 + i) * LDSTR + k];
#pragma unroll
            for (int j = 0; j < 4; j++) vc[j] = Vs[k * LDSTR + (c0 + j)];
#pragma unroll
            for (int i = 0; i < 4; i++)
#pragma unroll
                for (int j = 0; j < 4; j++)
                    o[i][j] = fmaf(pr[i], vc[j], o[i][j]);
        }
        __syncthreads();
    }

#pragma unroll
    for (int i = 0; i < 4; i++) {
        const float inv = 1.0f / l_i[i];
        const size_t row = (size_t)(b * S_ + q0 + r0 + i) * D_ + h * DH_ + c0;
#pragma unroll
        for (int j = 0; j < 4; j++)
            ctx[row + j] = o[i][j] * inv;
    }
}

// ---------------------------------------------------------------------------
extern "C" void kernel_launch(void* const* d_in, const int* in_sizes, int n_in,
                              void* d_out, int out_size)
{
    const float* x     = (const float*)d_in[0];
    // d_in[1] = mask (causal, implied) — unused
    const float* w_qkv = (const float*)d_in[2];
    const float* b_qkv = (const float*)d_in[3];
    const float* w_out = (const float*)d_in[4];
    const float* b_out = (const float*)d_in[5];
    float* out = (float*)d_out;

    float* ctx_ptr = nullptr;
    cudaGetSymbolAddress((void**)&ctx_ptr, g_ctx);

    // 1) QKV projection (tf32 mma.sync) with scatter epilogue
    {
        dim3 grid(N_QKV / 128, M_ / 128);
        mma_gemm<1><<<grid, 256>>>(x, w_qkv, b_qkv, nullptr, N_QKV, D_);
    }

    // 2) Causal attention (fp32 SIMT)
    {
        const int smem = 3 * 64 * LDSTR * (int)sizeof(float); // 49,920 B
        cudaFuncSetAttribute(attn_kernel,
                             cudaFuncAttributeMaxDynamicSharedMemorySize, smem);
        dim3 grid(S_ / 64, B_ * H_);
        attn_kernel<<<grid, 256, smem>>>(ctx_ptr);
    }

    // 3) Output projection (tf32 mma.sync)
    {
        dim3 grid(D_ / 128, M_ / 128);
        mma_gemm<0><<<grid, 256>>>(ctx_ptr, w_out, b_out, out, D_, D_);
    }
}

// round 5
// speedup vs baseline: 3.1604x; 1.9273x over previous
#include <cuda_runtime.h>
#include <cstdint>
#include <cstddef>

// Problem constants
#define B_ 4
#define S_ 2048
#define D_ 1024
#define H_ 16
#define DH_ 64
#define M_ (B_ * S_)      // 8192
#define N_QKV (3 * D_)    // 3072

// Scratch (device globals — no allocation allowed)
__device__ float g_q[(size_t)B_ * H_ * S_ * DH_];   // [B,H,S,Dh], tf32-rounded, Q pre-scaled 1/8
__device__ float g_k[(size_t)B_ * H_ * S_ * DH_];
__device__ float g_v[(size_t)B_ * H_ * S_ * DH_];
__device__ float g_ctx[(size_t)M_ * D_];            // [B,S,D]

// ---------------------------------------------------------------------------
// helpers
// ---------------------------------------------------------------------------
__device__ __forceinline__ uint32_t f2tf32(float f) {
    uint32_t r;
    asm("cvt.rna.tf32.f32 %0, %1;" : "=r"(r) : "f"(f));
    return r;
}
__device__ __forceinline__ float tf32r(float f) {
    return __uint_as_float(f2tf32(f));
}
__device__ __forceinline__ void mma_tf32(float* c, const uint32_t* a,
                                         const uint32_t* b) {
    asm volatile(
        "mma.sync.aligned.m16n8k8.row.col.f32.tf32.tf32.f32 "
        "{%0,%1,%2,%3}, {%4,%5,%6,%7}, {%8,%9}, {%0,%1,%2,%3};"
        : "+f"(c[0]), "+f"(c[1]), "+f"(c[2]), "+f"(c[3])
        : "r"(a[0]), "r"(a[1]), "r"(a[2]), "r"(a[3]), "r"(b[0]), "r"(b[1]));
}
__device__ __forceinline__ uint32_t smem_u32(const void* p) {
    uint32_t a;
    asm("{ .reg .u64 t; cvta.to.shared.u64 t, %1; cvt.u32.u64 %0, t; }"
        : "=r"(a) : "l"(p));
    return a;
}
__device__ __forceinline__ void cp16(uint32_t dst, const void* src) {
    asm volatile("cp.async.ca.shared.global [%0], [%1], 16;"
                 :: "r"(dst), "l"(src));
}
#define CP_COMMIT() asm volatile("cp.async.commit_group;" ::: "memory")
#define CP_WAIT(n)  asm volatile("cp.async.wait_group %0;" :: "n"(n) : "memory")

// swizzled float index within a 128x32-float tile (GEMM kernels)
__device__ __forceinline__ int swz_idx(int r, int c4) {
    return r * 32 + ((c4 ^ (r & 7)) << 2);
}

// ---------------------------------------------------------------------------
// Tensor-core GEMM (unchanged from R4 except tf32-rounded QKV scatter).
// ---------------------------------------------------------------------------
template <int EPI>
__global__ __launch_bounds__(256) void mma_gemm(
    const float* __restrict__ A, const float* __restrict__ W,
    const float* __restrict__ bias, float* __restrict__ C,
    int N, int K)
{
    __shared__ uint32_t As[128 * 32];
    __shared__ uint32_t Bs[128 * 32];

    const int tid = threadIdx.x;
    const int wid = tid >> 5;
    const int lane = tid & 31;
    const int g = lane >> 2;
    const int t = lane & 3;
    const int m0 = (wid >> 2) * 64;
    const int n0 = (wid & 3) * 32;

    const int bm = blockIdx.y * 128;
    const int bn = blockIdx.x * 128;

    const float* Ag = A + (size_t)bm * K;
    const float* Wg = W + (size_t)bn * K;

    const int lr  = tid >> 3;
    const int lc4 = tid & 7;

    float c[4][4][4];
#pragma unroll
    for (int i = 0; i < 4; i++)
#pragma unroll
        for (int j = 0; j < 4; j++)
#pragma unroll
            for (int q = 0; q < 4; q++) c[i][j][q] = 0.0f;

    float4 av[4], wv[4];

#pragma unroll
    for (int q = 0; q < 4; q++) {
        const int r = lr + 32 * q;
        av[q] = *(const float4*)(Ag + (size_t)r * K + lc4 * 4);
        wv[q] = *(const float4*)(Wg + (size_t)r * K + lc4 * 4);
    }
#pragma unroll
    for (int q = 0; q < 4; q++) {
        const int r = lr + 32 * q;
        const int off = swz_idx(r, lc4);
        As[off + 0] = f2tf32(av[q].x); As[off + 1] = f2tf32(av[q].y);
        As[off + 2] = f2tf32(av[q].z); As[off + 3] = f2tf32(av[q].w);
        Bs[off + 0] = f2tf32(wv[q].x); Bs[off + 1] = f2tf32(wv[q].y);
        Bs[off + 2] = f2tf32(wv[q].z); Bs[off + 3] = f2tf32(wv[q].w);
    }
    __syncthreads();

    const int NCH = K >> 5;
    for (int ch = 0; ch < NCH; ch++) {
        if (ch + 1 < NCH) {
            const int kc = (ch + 1) * 32;
#pragma unroll
            for (int q = 0; q < 4; q++) {
                const int r = lr + 32 * q;
                av[q] = *(const float4*)(Ag + (size_t)r * K + kc + lc4 * 4);
                wv[q] = *(const float4*)(Wg + (size_t)r * K + kc + lc4 * 4);
            }
        }
#pragma unroll
        for (int ks = 0; ks < 4; ks++) {
            const int kc = ks * 8;
            uint32_t afr[4][4];
#pragma unroll
            for (int mt = 0; mt < 4; mt++) {
                const int r = m0 + mt * 16 + g;
                const int r8 = r + 8;
                afr[mt][0] = As[r * 32 + ((((kc + t) >> 2) ^ (r & 7)) << 2) + (t & 3)];
                afr[mt][1] = As[r8 * 32 + ((((kc + t) >> 2) ^ (r8 & 7)) << 2) + (t & 3)];
                afr[mt][2] = As[r * 32 + ((((kc + 4 + t) >> 2) ^ (r & 7)) << 2) + (t & 3)];
                afr[mt][3] = As[r8 * 32 + ((((kc + 4 + t) >> 2) ^ (r8 & 7)) << 2) + (t & 3)];
            }
            uint32_t bfr[4][2];
#pragma unroll
            for (int nt = 0; nt < 4; nt++) {
                const int r = n0 + nt * 8 + g;
                bfr[nt][0] = Bs[r * 32 + ((((kc + t) >> 2) ^ (r & 7)) << 2) + (t & 3)];
                bfr[nt][1] = Bs[r * 32 + ((((kc + 4 + t) >> 2) ^ (r & 7)) << 2) + (t & 3)];
            }
#pragma unroll
            for (int mt = 0; mt < 4; mt++)
#pragma unroll
                for (int nt = 0; nt < 4; nt++)
                    mma_tf32(c[mt][nt], afr[mt], bfr[nt]);
        }
        __syncthreads();

        if (ch + 1 < NCH) {
#pragma unroll
            for (int q = 0; q < 4; q++) {
                const int r = lr + 32 * q;
                const int off = swz_idx(r, lc4);
                As[off + 0] = f2tf32(av[q].x); As[off + 1] = f2tf32(av[q].y);
                As[off + 2] = f2tf32(av[q].z); As[off + 3] = f2tf32(av[q].w);
                Bs[off + 0] = f2tf32(wv[q].x); Bs[off + 1] = f2tf32(wv[q].y);
                Bs[off + 2] = f2tf32(wv[q].z); Bs[off + 3] = f2tf32(wv[q].w);
            }
            __syncthreads();
        }
    }

#pragma unroll
    for (int mt = 0; mt < 4; mt++) {
#pragma unroll
        for (int half = 0; half < 2; half++) {
            const int m = bm + m0 + mt * 16 + g + half * 8;
#pragma unroll
            for (int nt = 0; nt < 4; nt++) {
                const int n = bn + n0 + nt * 8 + t * 2;
                const float v0 = c[mt][nt][half * 2 + 0] + bias[n + 0];
                const float v1 = c[mt][nt][half * 2 + 1] + bias[n + 1];
                if (EPI == 0) {
                    *(float2*)(C + (size_t)m * N + n) = make_float2(v0, v1);
                } else {
                    const int bb = m >> 11;
                    const int s  = m & 2047;
                    const int cg = n >> 10;
                    const int h  = (n & 1023) >> 6;
                    const int d  = n & 63;
                    const float sc = (cg == 0) ? 0.125f : 1.0f;
                    float* dst = (cg == 0) ? g_q : ((cg == 1) ? g_k : g_v);
                    float2 o = make_float2(tf32r(v0 * sc), tf32r(v1 * sc));
                    *(float2*)(dst + (((size_t)(bb * H_ + h)) * S_ + s) * DH_ + d) = o;
                }
            }
        }
    }
}

// ---------------------------------------------------------------------------
// Flash attention on mma.sync tf32.
// CTA: 128 Q rows of one (b,h). 8 warps, warp = 16 rows. KV chunks of 64 keys.
// Smem (floats): Q[128][68], K[2][64][68], V[2][64][72]. Total 106,496 B.
// ---------------------------------------------------------------------------
#define QSTR 68
#define KSTR 68
#define VSTR 72
#define QS_OFF  0
#define KS_OFF  (128 * QSTR)                 // 8704
#define KS_SZ   (64 * KSTR)                  // 4352
#define VS_OFF  (KS_OFF + 2 * KS_SZ)         // 17408
#define VS_SZ   (64 * VSTR)                  // 4608
#define ATT_SMEM ((VS_OFF + 2 * VS_SZ) * 4)  // 106496 B

__global__ __launch_bounds__(256) void attn_mma(float* __restrict__ ctx)
{
    extern __shared__ float sm[];
    uint32_t* smu = (uint32_t*)sm;
    const uint32_t smb = smem_u32(sm);

    const int qb = (int)gridDim.x - 1 - (int)blockIdx.x;  // heavy tiles first
    const int bh = blockIdx.y;
    const int b  = bh >> 4;
    const int h  = bh & 15;
    const size_t base = (size_t)bh * (S_ * DH_);
    const int q0 = qb * 128;

    const int tid  = threadIdx.x;
    const int wid  = tid >> 5;
    const int lane = tid & 31;
    const int g = lane >> 2;
    const int t = lane & 3;

    // ---- async load Q tile + KV chunk 0 (group 0) ----
#pragma unroll
    for (int it = 0; it < 8; it++) {
        const int idx = tid + 256 * it;
        const int r = idx >> 4, c4 = idx & 15;
        cp16(smb + (uint32_t)(QS_OFF + r * QSTR + c4 * 4) * 4,
             g_q + base + (size_t)(q0 + r) * DH_ + c4 * 4);
    }
#pragma unroll
    for (int it = 0; it < 4; it++) {
        const int idx = tid + 256 * it;
        const int r = idx >> 4, c4 = idx & 15;
        cp16(smb + (uint32_t)(KS_OFF + r * KSTR + c4 * 4) * 4,
             g_k + base + (size_t)r * DH_ + c4 * 4);
        cp16(smb + (uint32_t)(VS_OFF + r * VSTR + c4 * 4) * 4,
             g_v + base + (size_t)r * DH_ + c4 * 4);
    }
    CP_COMMIT();

    float o[8][4];
#pragma unroll
    for (int nt = 0; nt < 8; nt++)
#pragma unroll
        for (int j = 0; j < 4; j++) o[nt][j] = 0.0f;
    float m0r = -1e30f, m1r = -1e30f, l0r = 0.0f, l1r = 0.0f;

    const int nch = 2 * (qb + 1);
    const int aw = 16 * wid + g;          // A-fragment base row (Q)

    for (int c = 0; c < nch; c++) {
        const int cb = c & 1;
        // prefetch next chunk
        if (c + 1 < nch) {
            const int nb = (c + 1) & 1;
            const int koff = KS_OFF + nb * KS_SZ;
            const int voff = VS_OFF + nb * VS_SZ;
            const size_t kbase = base + (size_t)(c + 1) * 64 * DH_;
#pragma unroll
            for (int it = 0; it < 4; it++) {
                const int idx = tid + 256 * it;
                const int r = idx >> 4, c4 = idx & 15;
                cp16(smb + (uint32_t)(koff + r * KSTR + c4 * 4) * 4,
                     g_k + kbase + (size_t)r * DH_ + c4 * 4);
                cp16(smb + (uint32_t)(voff + r * VSTR + c4 * 4) * 4,
                     g_v + kbase + (size_t)r * DH_ + c4 * 4);
            }
            CP_COMMIT();
            CP_WAIT(1);
        } else {
            CP_WAIT(0);
        }
        __syncthreads();

        const int koff = KS_OFF + cb * KS_SZ;
        const int voff = VS_OFF + cb * VS_SZ;

        // ---- S = Q K^T ----
        float s[8][4];
#pragma unroll
        for (int nt = 0; nt < 8; nt++)
#pragma unroll
            for (int j = 0; j < 4; j++) s[nt][j] = 0.0f;

#pragma unroll
        for (int ks = 0; ks < 8; ks++) {
            const int kc = ks * 8;
            uint32_t a[4];
            a[0] = smu[aw * QSTR + kc + t];
            a[1] = smu[(aw + 8) * QSTR + kc + t];
            a[2] = smu[aw * QSTR + kc + 4 + t];
            a[3] = smu[(aw + 8) * QSTR + kc + 4 + t];
#pragma unroll
            for (int nt = 0; nt < 8; nt++) {
                uint32_t bfr[2];
                bfr[0] = smu[koff + (8 * nt + g) * KSTR + kc + t];
                bfr[1] = smu[koff + (8 * nt + g) * KSTR + kc + 4 + t];
                mma_tf32(s[nt], a, bfr);
            }
        }

        // ---- causal mask (last two chunks only) ----
        if (c * 64 + 63 > q0) {
            const int row0 = q0 + aw;
            const int row1 = row0 + 8;
            const int colb = c * 64 + 2 * t;
#pragma unroll
            for (int nt = 0; nt < 8; nt++) {
                const int col = colb + 8 * nt;
                if (col > row0)     s[nt][0] = -1e30f;
                if (col + 1 > row0) s[nt][1] = -1e30f;
                if (col > row1)     s[nt][2] = -1e30f;
                if (col + 1 > row1) s[nt][3] = -1e30f;
            }
        }

        // ---- online softmax (rows g and g+8; quad reduction) ----
        float mn0 = -1e30f, mn1 = -1e30f;
#pragma unroll
        for (int nt = 0; nt < 8; nt++) {
            mn0 = fmaxf(mn0, fmaxf(s[nt][0], s[nt][1]));
            mn1 = fmaxf(mn1, fmaxf(s[nt][2], s[nt][3]));
        }
        mn0 = fmaxf(mn0, __shfl_xor_sync(0xffffffffu, mn0, 1));
        mn0 = fmaxf(mn0, __shfl_xor_sync(0xffffffffu, mn0, 2));
        mn1 = fmaxf(mn1, __shfl_xor_sync(0xffffffffu, mn1, 1));
        mn1 = fmaxf(mn1, __shfl_xor_sync(0xffffffffu, mn1, 2));
        const float mN0 = fmaxf(m0r, mn0);
        const float mN1 = fmaxf(m1r, mn1);
        const float sc0 = __expf(m0r - mN0);
        const float sc1 = __expf(m1r - mN1);
        m0r = mN0; m1r = mN1;

        float rs0 = 0.0f, rs1 = 0.0f;
#pragma unroll
        for (int nt = 0; nt < 8; nt++) {
            s[nt][0] = __expf(s[nt][0] - mN0); rs0 += s[nt][0];
            s[nt][1] = __expf(s[nt][1] - mN0); rs0 += s[nt][1];
            s[nt][2] = __expf(s[nt][2] - mN1); rs1 += s[nt][2];
            s[nt][3] = __expf(s[nt][3] - mN1); rs1 += s[nt][3];
        }
        rs0 += __shfl_xor_sync(0xffffffffu, rs0, 1);
        rs0 += __shfl_xor_sync(0xffffffffu, rs0, 2);
        rs1 += __shfl_xor_sync(0xffffffffu, rs1, 1);
        rs1 += __shfl_xor_sync(0xffffffffu, rs1, 2);
        l0r = l0r * sc0 + rs0;
        l1r = l1r * sc1 + rs1;
#pragma unroll
        for (int nt = 0; nt < 8; nt++) {
            o[nt][0] *= sc0; o[nt][1] *= sc0;
            o[nt][2] *= sc1; o[nt][3] *= sc1;
        }

        // ---- O += P V : convert C-layout P to A-fragments via quad shuffles ----
        const int qbase = lane & ~3;
        const int src0 = qbase + (t >> 1);
        const int src1 = src0 + 2;
#pragma unroll
        for (int ks = 0; ks < 8; ks++) {
            const uint32_t pc0 = f2tf32(s[ks][0]);
            const uint32_t pc1 = f2tf32(s[ks][1]);
            const uint32_t pc2 = f2tf32(s[ks][2]);
            const uint32_t pc3 = f2tf32(s[ks][3]);
            uint32_t a[4];
            {
                const uint32_t x0 = __shfl_sync(0xffffffffu, pc0, src0);
                const uint32_t x1 = __shfl_sync(0xffffffffu, pc1, src0);
                a[0] = (t & 1) ? x1 : x0;
                const uint32_t y0 = __shfl_sync(0xffffffffu, pc2, src0);
                const uint32_t y1 = __shfl_sync(0xffffffffu, pc3, src0);
                a[1] = (t & 1) ? y1 : y0;
                const uint32_t z0 = __shfl_sync(0xffffffffu, pc0, src1);
                const uint32_t z1 = __shfl_sync(0xffffffffu, pc1, src1);
                a[2] = (t & 1) ? z1 : z0;
                const uint32_t w0 = __shfl_sync(0xffffffffu, pc2, src1);
                const uint32_t w1 = __shfl_sync(0xffffffffu, pc3, src1);
                a[3] = (t & 1) ? w1 : w0;
            }
            const int kc = ks * 8;
#pragma unroll
            for (int nt = 0; nt < 8; nt++) {
                uint32_t bfr[2];
                bfr[0] = smu[voff + (kc + t) * VSTR + 8 * nt + g];
                bfr[1] = smu[voff + (kc + 4 + t) * VSTR + 8 * nt + g];
                mma_tf32(o[nt], a, bfr);
            }
        }
        __syncthreads();   // all warps done with this KV buffer
    }

    // ---- epilogue: ctx[b][q0+row][h*64 + d] ----
    const float inv0 = 1.0f / l0r;
    const float inv1 = 1.0f / l1r;
    const int row0 = q0 + aw;
    float* dst0 = ctx + ((size_t)(b * S_) + row0) * D_ + h * DH_ + 2 * t;
    float* dst1 = dst0 + 8 * D_;
#pragma unroll
    for (int nt = 0; nt < 8; nt++) {
        *(float2*)(dst0 + 8 * nt) = make_float2(o[nt][0] * inv0, o[nt][1] * inv0);
        *(float2*)(dst1 + 8 * nt) = make_float2(o[nt][2] * inv1, o[nt][3] * inv1);
    }
}

// ---------------------------------------------------------------------------
extern "C" void kernel_launch(void* const* d_in, const int* in_sizes, int n_in,
                              void* d_out, int out_size)
{
    const float* x     = (const float*)d_in[0];
    // d_in[1] = mask (causal, implied) — unused
    const float* w_qkv = (const float*)d_in[2];
    const float* b_qkv = (const float*)d_in[3];
    const float* w_out = (const float*)d_in[4];
    const float* b_out = (const float*)d_in[5];
    float* out = (float*)d_out;

    float* ctx_ptr = nullptr;
    cudaGetSymbolAddress((void**)&ctx_ptr, g_ctx);

    // 1) QKV projection (tf32 mma.sync) with tf32-rounded scatter epilogue
    {
        dim3 grid(N_QKV / 128, M_ / 128);
        mma_gemm<1><<<grid, 256>>>(x, w_qkv, b_qkv, nullptr, N_QKV, D_);
    }

    // 2) Causal flash attention (tf32 mma.sync)
    {
        cudaFuncSetAttribute(attn_mma,
                             cudaFuncAttributeMaxDynamicSharedMemorySize, ATT_SMEM);
        dim3 grid(S_ / 128, B_ * H_);
        attn_mma<<<grid, 256, ATT_SMEM>>>(ctx_ptr);
    }

    // 3) Output projection (tf32 mma.sync)
    {
        dim3 grid(D_ / 128, M_ / 128);
        mma_gemm<0><<<grid, 256>>>(ctx_ptr, w_out, b_out, out, D_, D_);
    }
}

// round 6
// speedup vs baseline: 3.4194x; 1.0819x over previous
#include <cuda_runtime.h>
#include <cstdint>
#include <cstddef>

// Problem constants
#define B_ 4
#define S_ 2048
#define D_ 1024
#define H_ 16
#define DH_ 64
#define M_ (B_ * S_)      // 8192
#define N_QKV (3 * D_)    // 3072

// Scratch (device globals — no allocation allowed)
__device__ float g_q[(size_t)B_ * H_ * S_ * DH_];   // [B,H,S,Dh], tf32-rounded, Q pre-scaled 1/8
__device__ float g_k[(size_t)B_ * H_ * S_ * DH_];
__device__ float g_v[(size_t)B_ * H_ * S_ * DH_];
__device__ float g_ctx[(size_t)M_ * D_];            // [B,S,D]

// ---------------------------------------------------------------------------
// helpers
// ---------------------------------------------------------------------------
__device__ __forceinline__ uint32_t f2tf32(float f) {
    uint32_t r;
    asm("cvt.rna.tf32.f32 %0, %1;" : "=r"(r) : "f"(f));
    return r;
}
__device__ __forceinline__ float tf32r(float f) {
    return __uint_as_float(f2tf32(f));
}
__device__ __forceinline__ void mma_tf32(float* c, const uint32_t* a,
                                         const uint32_t* b) {
    asm volatile(
        "mma.sync.aligned.m16n8k8.row.col.f32.tf32.tf32.f32 "
        "{%0,%1,%2,%3}, {%4,%5,%6,%7}, {%8,%9}, {%0,%1,%2,%3};"
        : "+f"(c[0]), "+f"(c[1]), "+f"(c[2]), "+f"(c[3])
        : "r"(a[0]), "r"(a[1]), "r"(a[2]), "r"(a[3]), "r"(b[0]), "r"(b[1]));
}
__device__ __forceinline__ uint32_t smem_u32(const void* p) {
    uint32_t a;
    asm("{ .reg .u64 t; cvta.to.shared.u64 t, %1; cvt.u32.u64 %0, t; }"
        : "=r"(a) : "l"(p));
    return a;
}
__device__ __forceinline__ void cp16(uint32_t dst, const void* src) {
    asm volatile("cp.async.ca.shared.global [%0], [%1], 16;"
                 :: "r"(dst), "l"(src));
}
#define CP_COMMIT() asm volatile("cp.async.commit_group;" ::: "memory")
#define CP_WAIT(n)  asm volatile("cp.async.wait_group %0;" :: "n"(n) : "memory")

// swizzled float index within a 128x32-float tile (write side)
__device__ __forceinline__ int swz_idx(int r, int c4) {
    return r * 32 + ((c4 ^ (r & 7)) << 2);
}

// ---------------------------------------------------------------------------
// Tensor-core GEMM: C[m,n] = sum_k A[m,k] * W[n,k] + bias[n]
// Tile 128x128, BK=32, 8 warps (2m x 4n), warp tile 64x32, m16n8k8 tf32.
// Double-buffered smem (one barrier per chunk), software-pipelined
// fragment loads, XOR-addressed fragment offsets.
// Dynamic smem: 2 * (As 16KB + Bs 16KB) = 65536 B.
// EPI=0: plain store.  EPI=1: scatter to g_q/g_k/g_v (Q scaled 1/8, tf32-rounded).
// ---------------------------------------------------------------------------
template <int EPI>
__global__ __launch_bounds__(256) void mma_gemm(
    const float* __restrict__ A, const float* __restrict__ W,
    const float* __restrict__ bias, float* __restrict__ C,
    int N, int K)
{
    extern __shared__ uint32_t dsm[];   // [2][8192]: per buffer As(4096) + Bs(4096)

    const int tid = threadIdx.x;
    const int wid = tid >> 5;
    const int lane = tid & 31;
    const int g = lane >> 2;
    const int t = lane & 3;
    const int m0 = (wid >> 2) * 64;
    const int n0 = (wid & 3) * 32;

    const int bm = blockIdx.y * 128;
    const int bn = blockIdx.x * 128;

    const float* Ag = A + (size_t)bm * K;
    const float* Wg = W + (size_t)bn * K;

    const int lr  = tid >> 3;     // loader row 0..31 (+32q)
    const int lc4 = tid & 7;      // float4 col in 128B row

    // Fragment base offsets: addr(word) = D ^ (ks<<3) [^4 for upper half-k]
    int Da[4][2], Db[4];
#pragma unroll
    for (int mt = 0; mt < 4; mt++) {
        int r = m0 + mt * 16 + g;
        Da[mt][0] = (r * 32 + t) ^ ((r & 7) << 2);
        r += 8;
        Da[mt][1] = (r * 32 + t) ^ ((r & 7) << 2);
    }
#pragma unroll
    for (int nt = 0; nt < 4; nt++) {
        const int r = n0 + nt * 8 + g;
        Db[nt] = (r * 32 + t) ^ ((r & 7) << 2);
    }

    float c[4][4][4];
#pragma unroll
    for (int i = 0; i < 4; i++)
#pragma unroll
        for (int j = 0; j < 4; j++)
#pragma unroll
            for (int q = 0; q < 4; q++) c[i][j][q] = 0.0f;

    float4 av[4], wv[4];

    // ---- preload chunk 0 into buffer 0 ----
#pragma unroll
    for (int q = 0; q < 4; q++) {
        const int r = lr + 32 * q;
        av[q] = *(const float4*)(Ag + (size_t)r * K + lc4 * 4);
        wv[q] = *(const float4*)(Wg + (size_t)r * K + lc4 * 4);
    }
#pragma unroll
    for (int q = 0; q < 4; q++) {
        const int r = lr + 32 * q;
        const int off = swz_idx(r, lc4);
        dsm[off + 0] = f2tf32(av[q].x); dsm[off + 1] = f2tf32(av[q].y);
        dsm[off + 2] = f2tf32(av[q].z); dsm[off + 3] = f2tf32(av[q].w);
        dsm[4096 + off + 0] = f2tf32(wv[q].x); dsm[4096 + off + 1] = f2tf32(wv[q].y);
        dsm[4096 + off + 2] = f2tf32(wv[q].z); dsm[4096 + off + 3] = f2tf32(wv[q].w);
    }
    __syncthreads();

    const int NCH = K >> 5;   // 32
    for (int ch = 0; ch < NCH; ch++) {
        const uint32_t* As = dsm + (ch & 1) * 8192;
        const uint32_t* Bs = As + 4096;
        const bool more = (ch + 1 < NCH);

        // issue next chunk's global loads early (latency hidden under MMAs)
        if (more) {
            const int kc = (ch + 1) * 32;
#pragma unroll
            for (int q = 0; q < 4; q++) {
                const int r = lr + 32 * q;
                av[q] = *(const float4*)(Ag + (size_t)r * K + kc + lc4 * 4);
                wv[q] = *(const float4*)(Wg + (size_t)r * K + kc + lc4 * 4);
            }
        }

        // software-pipelined fragments: load ks+1 while MMA on ks
        uint32_t afr[2][4][4];
        uint32_t bfr[2][4][2];
        {
            const int kx0 = 0, kx1 = 4;
#pragma unroll
            for (int mt = 0; mt < 4; mt++) {
                afr[0][mt][0] = As[Da[mt][0] ^ kx0];
                afr[0][mt][1] = As[Da[mt][1] ^ kx0];
                afr[0][mt][2] = As[Da[mt][0] ^ kx1];
                afr[0][mt][3] = As[Da[mt][1] ^ kx1];
            }
#pragma unroll
            for (int nt = 0; nt < 4; nt++) {
                bfr[0][nt][0] = Bs[Db[nt] ^ kx0];
                bfr[0][nt][1] = Bs[Db[nt] ^ kx1];
            }
        }
#pragma unroll
        for (int ks = 0; ks < 4; ks++) {
            const int cur = ks & 1;
            if (ks < 3) {
                const int nxt = cur ^ 1;
                const int kx0 = (ks + 1) << 3;
                const int kx1 = kx0 | 4;
#pragma unroll
                for (int mt = 0; mt < 4; mt++) {
                    afr[nxt][mt][0] = As[Da[mt][0] ^ kx0];
                    afr[nxt][mt][1] = As[Da[mt][1] ^ kx0];
                    afr[nxt][mt][2] = As[Da[mt][0] ^ kx1];
                    afr[nxt][mt][3] = As[Da[mt][1] ^ kx1];
                }
#pragma unroll
                for (int nt = 0; nt < 4; nt++) {
                    bfr[nxt][nt][0] = Bs[Db[nt] ^ kx0];
                    bfr[nxt][nt][1] = Bs[Db[nt] ^ kx1];
                }
            }
#pragma unroll
            for (int mt = 0; mt < 4; mt++)
#pragma unroll
                for (int nt = 0; nt < 4; nt++)
                    mma_tf32(c[mt][nt], afr[cur][mt], bfr[cur][nt]);
        }

        // store staged regs into the other buffer; single barrier per chunk
        if (more) {
            uint32_t* Ad = dsm + ((ch + 1) & 1) * 8192;
            uint32_t* Bd = Ad + 4096;
#pragma unroll
            for (int q = 0; q < 4; q++) {
                const int r = lr + 32 * q;
                const int off = swz_idx(r, lc4);
                Ad[off + 0] = f2tf32(av[q].x); Ad[off + 1] = f2tf32(av[q].y);
                Ad[off + 2] = f2tf32(av[q].z); Ad[off + 3] = f2tf32(av[q].w);
                Bd[off + 0] = f2tf32(wv[q].x); Bd[off + 1] = f2tf32(wv[q].y);
                Bd[off + 2] = f2tf32(wv[q].z); Bd[off + 3] = f2tf32(wv[q].w);
            }
        }
        __syncthreads();
    }

    // ---- epilogue ----
#pragma unroll
    for (int mt = 0; mt < 4; mt++) {
#pragma unroll
        for (int half = 0; half < 2; half++) {
            const int m = bm + m0 + mt * 16 + g + half * 8;
#pragma unroll
            for (int nt = 0; nt < 4; nt++) {
                const int n = bn + n0 + nt * 8 + t * 2;
                const float v0 = c[mt][nt][half * 2 + 0] + bias[n + 0];
                const float v1 = c[mt][nt][half * 2 + 1] + bias[n + 1];
                if (EPI == 0) {
                    *(float2*)(C + (size_t)m * N + n) = make_float2(v0, v1);
                } else {
                    const int bb = m >> 11;
                    const int s  = m & 2047;
                    const int cg = n >> 10;
                    const int h  = (n & 1023) >> 6;
                    const int d  = n & 63;
                    const float sc = (cg == 0) ? 0.125f : 1.0f;
                    float* dst = (cg == 0) ? g_q : ((cg == 1) ? g_k : g_v);
                    float2 o = make_float2(tf32r(v0 * sc), tf32r(v1 * sc));
                    *(float2*)(dst + (((size_t)(bb * H_ + h)) * S_ + s) * DH_ + d) = o;
                }
            }
        }
    }
}

#define GEMM_SMEM (2 * 8192 * 4)   // 65536 B

// ---------------------------------------------------------------------------
// Flash attention on mma.sync tf32 (unchanged from R5).
// CTA: 128 Q rows of one (b,h). 8 warps, warp = 16 rows. KV chunks of 64 keys.
// Smem (floats): Q[128][68], K[2][64][68], V[2][64][72]. Total 106,496 B.
// ---------------------------------------------------------------------------
#define QSTR 68
#define KSTR 68
#define VSTR 72
#define QS_OFF  0
#define KS_OFF  (128 * QSTR)                 // 8704
#define KS_SZ   (64 * KSTR)                  // 4352
#define VS_OFF  (KS_OFF + 2 * KS_SZ)         // 17408
#define VS_SZ   (64 * VSTR)                  // 4608
#define ATT_SMEM ((VS_OFF + 2 * VS_SZ) * 4)  // 106496 B

__global__ __launch_bounds__(256) void attn_mma(float* __restrict__ ctx)
{
    extern __shared__ float sm[];
    uint32_t* smu = (uint32_t*)sm;
    const uint32_t smb = smem_u32(sm);

    const int qb = (int)gridDim.x - 1 - (int)blockIdx.x;  // heavy tiles first
    const int bh = blockIdx.y;
    const int b  = bh >> 4;
    const int h  = bh & 15;
    const size_t base = (size_t)bh * (S_ * DH_);
    const int q0 = qb * 128;

    const int tid  = threadIdx.x;
    const int wid  = tid >> 5;
    const int lane = tid & 31;
    const int g = lane >> 2;
    const int t = lane & 3;

    // ---- async load Q tile + KV chunk 0 ----
#pragma unroll
    for (int it = 0; it < 8; it++) {
        const int idx = tid + 256 * it;
        const int r = idx >> 4, c4 = idx & 15;
        cp16(smb + (uint32_t)(QS_OFF + r * QSTR + c4 * 4) * 4,
             g_q + base + (size_t)(q0 + r) * DH_ + c4 * 4);
    }
#pragma unroll
    for (int it = 0; it < 4; it++) {
        const int idx = tid + 256 * it;
        const int r = idx >> 4, c4 = idx & 15;
        cp16(smb + (uint32_t)(KS_OFF + r * KSTR + c4 * 4) * 4,
             g_k + base + (size_t)r * DH_ + c4 * 4);
        cp16(smb + (uint32_t)(VS_OFF + r * VSTR + c4 * 4) * 4,
             g_v + base + (size_t)r * DH_ + c4 * 4);
    }
    CP_COMMIT();

    float o[8][4];
#pragma unroll
    for (int nt = 0; nt < 8; nt++)
#pragma unroll
        for (int j = 0; j < 4; j++) o[nt][j] = 0.0f;
    float m0r = -1e30f, m1r = -1e30f, l0r = 0.0f, l1r = 0.0f;

    const int nch = 2 * (qb + 1);
    const int aw = 16 * wid + g;          // A-fragment base row (Q)

    for (int c = 0; c < nch; c++) {
        const int cb = c & 1;
        if (c + 1 < nch) {
            const int nb = (c + 1) & 1;
            const int koff = KS_OFF + nb * KS_SZ;
            const int voff = VS_OFF + nb * VS_SZ;
            const size_t kbase = base + (size_t)(c + 1) * 64 * DH_;
#pragma unroll
            for (int it = 0; it < 4; it++) {
                const int idx = tid + 256 * it;
                const int r = idx >> 4, c4 = idx & 15;
                cp16(smb + (uint32_t)(koff + r * KSTR + c4 * 4) * 4,
                     g_k + kbase + (size_t)r * DH_ + c4 * 4);
                cp16(smb + (uint32_t)(voff + r * VSTR + c4 * 4) * 4,
                     g_v + kbase + (size_t)r * DH_ + c4 * 4);
            }
            CP_COMMIT();
            CP_WAIT(1);
        } else {
            CP_WAIT(0);
        }
        __syncthreads();

        const int koff = KS_OFF + cb * KS_SZ;
        const int voff = VS_OFF + cb * VS_SZ;

        // ---- S = Q K^T ----
        float s[8][4];
#pragma unroll
        for (int nt = 0; nt < 8; nt++)
#pragma unroll
            for (int j = 0; j < 4; j++) s[nt][j] = 0.0f;

#pragma unroll
        for (int ks = 0; ks < 8; ks++) {
            const int kc = ks * 8;
            uint32_t a[4];
            a[0] = smu[aw * QSTR + kc + t];
            a[1] = smu[(aw + 8) * QSTR + kc + t];
            a[2] = smu[aw * QSTR + kc + 4 + t];
            a[3] = smu[(aw + 8) * QSTR + kc + 4 + t];
#pragma unroll
            for (int nt = 0; nt < 8; nt++) {
                uint32_t bfr[2];
                bfr[0] = smu[koff + (8 * nt + g) * KSTR + kc + t];
                bfr[1] = smu[koff + (8 * nt + g) * KSTR + kc + 4 + t];
                mma_tf32(s[nt], a, bfr);
            }
        }

        // ---- causal mask (diagonal chunks only) ----
        if (c * 64 + 63 > q0) {
            const int row0 = q0 + aw;
            const int row1 = row0 + 8;
            const int colb = c * 64 + 2 * t;
#pragma unroll
            for (int nt = 0; nt < 8; nt++) {
                const int col = colb + 8 * nt;
                if (col > row0)     s[nt][0] = -1e30f;
                if (col + 1 > row0) s[nt][1] = -1e30f;
                if (col > row1)     s[nt][2] = -1e30f;
                if (col + 1 > row1) s[nt][3] = -1e30f;
            }
        }

        // ---- online softmax ----
        float mn0 = -1e30f, mn1 = -1e30f;
#pragma unroll
        for (int nt = 0; nt < 8; nt++) {
            mn0 = fmaxf(mn0, fmaxf(s[nt][0], s[nt][1]));
            mn1 = fmaxf(mn1, fmaxf(s[nt][2], s[nt][3]));
        }
        mn0 = fmaxf(mn0, __shfl_xor_sync(0xffffffffu, mn0, 1));
        mn0 = fmaxf(mn0, __shfl_xor_sync(0xffffffffu, mn0, 2));
        mn1 = fmaxf(mn1, __shfl_xor_sync(0xffffffffu, mn1, 1));
        mn1 = fmaxf(mn1, __shfl_xor_sync(0xffffffffu, mn1, 2));
        const float mN0 = fmaxf(m0r, mn0);
        const float mN1 = fmaxf(m1r, mn1);
        const float sc0 = __expf(m0r - mN0);
        const float sc1 = __expf(m1r - mN1);
        m0r = mN0; m1r = mN1;

        float rs0 = 0.0f, rs1 = 0.0f;
#pragma unroll
        for (int nt = 0; nt < 8; nt++) {
            s[nt][0] = __expf(s[nt][0] - mN0); rs0 += s[nt][0];
            s[nt][1] = __expf(s[nt][1] - mN0); rs0 += s[nt][1];
            s[nt][2] = __expf(s[nt][2] - mN1); rs1 += s[nt][2];
            s[nt][3] = __expf(s[nt][3] - mN1); rs1 += s[nt][3];
        }
        rs0 += __shfl_xor_sync(0xffffffffu, rs0, 1);
        rs0 += __shfl_xor_sync(0xffffffffu, rs0, 2);
        rs1 += __shfl_xor_sync(0xffffffffu, rs1, 1);
        rs1 += __shfl_xor_sync(0xffffffffu, rs1, 2);
        l0r = l0r * sc0 + rs0;
        l1r = l1r * sc1 + rs1;
#pragma unroll
        for (int nt = 0; nt < 8; nt++) {
            o[nt][0] *= sc0; o[nt][1] *= sc0;
            o[nt][2] *= sc1; o[nt][3] *= sc1;
        }

        // ---- O += P V : C-layout -> A-fragment via quad shuffles ----
        const int qbase = lane & ~3;
        const int src0 = qbase + (t >> 1);
        const int src1 = src0 + 2;
#pragma unroll
        for (int ks = 0; ks < 8; ks++) {
            const uint32_t pc0 = f2tf32(s[ks][0]);
            const uint32_t pc1 = f2tf32(s[ks][1]);
            const uint32_t pc2 = f2tf32(s[ks][2]);
            const uint32_t pc3 = f2tf32(s[ks][3]);
            uint32_t a[4];
            {
                const uint32_t x0 = __shfl_sync(0xffffffffu, pc0, src0);
                const uint32_t x1 = __shfl_sync(0xffffffffu, pc1, src0);
                a[0] = (t & 1) ? x1 : x0;
                const uint32_t y0 = __shfl_sync(0xffffffffu, pc2, src0);
                const uint32_t y1 = __shfl_sync(0xffffffffu, pc3, src0);
                a[1] = (t & 1) ? y1 : y0;
                const uint32_t z0 = __shfl_sync(0xffffffffu, pc0, src1);
                const uint32_t z1 = __shfl_sync(0xffffffffu, pc1, src1);
                a[2] = (t & 1) ? z1 : z0;
                const uint32_t w0 = __shfl_sync(0xffffffffu, pc2, src1);
                const uint32_t w1 = __shfl_sync(0xffffffffu, pc3, src1);
                a[3] = (t & 1) ? w1 : w0;
            }
            const int kc = ks * 8;
#pragma unroll
            for (int nt = 0; nt < 8; nt++) {
                uint32_t bfr[2];
                bfr[0] = smu[voff + (kc + t) * VSTR + 8 * nt + g];
                bfr[1] = smu[voff + (kc + 4 + t) * VSTR + 8 * nt + g];
                mma_tf32(o[nt], a, bfr);
            }
        }
        __syncthreads();
    }

    // ---- epilogue ----
    const float inv0 = 1.0f / l0r;
    const float inv1 = 1.0f / l1r;
    const int row0 = q0 + aw;
    float* dst0 = ctx + ((size_t)(b * S_) + row0) * D_ + h * DH_ + 2 * t;
    float* dst1 = dst0 + 8 * D_;
#pragma unroll
    for (int nt = 0; nt < 8; nt++) {
        *(float2*)(dst0 + 8 * nt) = make_float2(o[nt][0] * inv0, o[nt][1] * inv0);
        *(float2*)(dst1 + 8 * nt) = make_float2(o[nt][2] * inv1, o[nt][3] * inv1);
    }
}

// ---------------------------------------------------------------------------
extern "C" void kernel_launch(void* const* d_in, const int* in_sizes, int n_in,
                              void* d_out, int out_size)
{
    const float* x     = (const float*)d_in[0];
    // d_in[1] = mask (causal, implied) — unused
    const float* w_qkv = (const float*)d_in[2];
    const float* b_qkv = (const float*)d_in[3];
    const float* w_out = (const float*)d_in[4];
    const float* b_out = (const float*)d_in[5];
    float* out = (float*)d_out;

    float* ctx_ptr = nullptr;
    cudaGetSymbolAddress((void**)&ctx_ptr, g_ctx);

    // 1) QKV projection (tf32 mma.sync, double-buffered) with scatter epilogue
    {
        cudaFuncSetAttribute(mma_gemm<1>,
                             cudaFuncAttributeMaxDynamicSharedMemorySize, GEMM_SMEM);
        dim3 grid(N_QKV / 128, M_ / 128);
        mma_gemm<1><<<grid, 256, GEMM_SMEM>>>(x, w_qkv, b_qkv, nullptr, N_QKV, D_);
    }

    // 2) Causal flash attention (tf32 mma.sync)
    {
        cudaFuncSetAttribute(attn_mma,
                             cudaFuncAttributeMaxDynamicSharedMemorySize, ATT_SMEM);
        dim3 grid(S_ / 128, B_ * H_);
        attn_mma<<<grid, 256, ATT_SMEM>>>(ctx_ptr);
    }

    // 3) Output projection (tf32 mma.sync, double-buffered)
    {
        cudaFuncSetAttribute(mma_gemm<0>,
                             cudaFuncAttributeMaxDynamicSharedMemorySize, GEMM_SMEM);
        dim3 grid(D_ / 128, M_ / 128);
        mma_gemm<0><<<grid, 256, GEMM_SMEM>>>(ctx_ptr, w_out, b_out, out, D_, D_);
    }
}

// round 7
// speedup vs baseline: 3.7519x; 1.0972x over previous
#include <cuda_runtime.h>
#include <cstdint>
#include <cstddef>

// Problem constants
#define B_ 4
#define S_ 2048
#define D_ 1024
#define H_ 16
#define DH_ 64
#define M_ (B_ * S_)      // 8192
#define N_QKV (3 * D_)    // 3072

// Scratch (device globals — no allocation allowed)
__device__ float g_q[(size_t)B_ * H_ * S_ * DH_];   // [B,H,S,Dh], tf32, Q pre-scaled 1/8
__device__ float g_k[(size_t)B_ * H_ * S_ * DH_];
__device__ float g_v[(size_t)B_ * H_ * S_ * DH_];
__device__ float g_ctx[(size_t)M_ * D_];            // [B,S,D], tf32-rounded
__device__ float g_x[(size_t)M_ * D_];              // tf32-rounded x
__device__ float g_wqkv[(size_t)N_QKV * D_];        // tf32-rounded w_qkv
__device__ float g_wout[(size_t)D_ * D_];           // tf32-rounded w_out

// ---------------------------------------------------------------------------
// helpers
// ---------------------------------------------------------------------------
__device__ __forceinline__ uint32_t f2tf32(float f) {
    uint32_t r;
    asm("cvt.rna.tf32.f32 %0, %1;" : "=r"(r) : "f"(f));
    return r;
}
__device__ __forceinline__ float tf32r(float f) {
    return __uint_as_float(f2tf32(f));
}
__device__ __forceinline__ void mma_tf32(float* c, const uint32_t* a,
                                         const uint32_t* b) {
    asm volatile(
        "mma.sync.aligned.m16n8k8.row.col.f32.tf32.tf32.f32 "
        "{%0,%1,%2,%3}, {%4,%5,%6,%7}, {%8,%9}, {%0,%1,%2,%3};"
        : "+f"(c[0]), "+f"(c[1]), "+f"(c[2]), "+f"(c[3])
        : "r"(a[0]), "r"(a[1]), "r"(a[2]), "r"(a[3]), "r"(b[0]), "r"(b[1]));
}
__device__ __forceinline__ uint32_t smem_u32(const void* p) {
    uint32_t a;
    asm("{ .reg .u64 t; cvta.to.shared.u64 t, %1; cvt.u32.u64 %0, t; }"
        : "=r"(a) : "l"(p));
    return a;
}
__device__ __forceinline__ void cp16(uint32_t dst, const void* src) {
    asm volatile("cp.async.ca.shared.global [%0], [%1], 16;"
                 :: "r"(dst), "l"(src));
}
#define CP_COMMIT() asm volatile("cp.async.commit_group;" ::: "memory")
#define CP_WAIT(n)  asm volatile("cp.async.wait_group %0;" :: "n"(n) : "memory")

// swizzled float index within a 128x32-float tile
__device__ __forceinline__ int swz_idx(int r, int c4) {
    return r * 32 + ((c4 ^ (r & 7)) << 2);
}

// ---------------------------------------------------------------------------
// tf32 rounding pre-pass (memory bound)
// ---------------------------------------------------------------------------
__global__ void tf32_round_kernel(const float* __restrict__ src,
                                  float* __restrict__ dst, int n4)
{
    const int i = blockIdx.x * blockDim.x + threadIdx.x;
    if (i < n4) {
        float4 v = ((const float4*)src)[i];
        v.x = tf32r(v.x); v.y = tf32r(v.y);
        v.z = tf32r(v.z); v.w = tf32r(v.w);
        ((float4*)dst)[i] = v;
    }
}

// ---------------------------------------------------------------------------
// Tensor-core GEMM v3: inputs pre-rounded to tf32.
// C[m,n] = sum_k A[m,k]*W[n,k] + bias[n]. Tile 128x128, BK=32,
// 8 warps (2m x 4n), warp tile 64x32, m16n8k8.
// cp.async G->S (no register staging, no cvt), 2-stage smem, 1 barrier/chunk.
// Dynamic smem: 2 * 32KB = 65536 B. 2 CTAs/SM.
// ---------------------------------------------------------------------------
template <int EPI>
__global__ __launch_bounds__(256, 2) void mma_gemm(
    const float* __restrict__ A, const float* __restrict__ W,
    const float* __restrict__ bias, float* __restrict__ C,
    int N, int K)
{
    extern __shared__ uint32_t dsm[];   // [2][8192] words: As(4096)+Bs(4096) per stage
    const uint32_t smb = smem_u32(dsm);

    const int tid = threadIdx.x;
    const int wid = tid >> 5;
    const int lane = tid & 31;
    const int g = lane >> 2;
    const int t = lane & 3;
    const int m0 = (wid >> 2) * 64;
    const int n0 = (wid & 3) * 32;

    const int bm = blockIdx.y * 128;
    const int bn = blockIdx.x * 128;

    const float* Ag = A + (size_t)bm * K;
    const float* Wg = W + (size_t)bn * K;

    const int lr  = tid >> 3;     // loader row 0..31 (+32q)
    const int lc4 = tid & 7;      // float4 col in 128B row
    // precomputed swizzled smem byte offsets for the 4 rows this thread loads
    uint32_t soff[4];
#pragma unroll
    for (int q = 0; q < 4; q++)
        soff[q] = (uint32_t)swz_idx(lr + 32 * q, lc4) * 4;

    // fragment base word-offsets (xor addressing)
    int Da[4][2], Db[4];
#pragma unroll
    for (int mt = 0; mt < 4; mt++) {
        int r = m0 + mt * 16 + g;
        Da[mt][0] = (r * 32 + t) ^ ((r & 7) << 2);
        r += 8;
        Da[mt][1] = (r * 32 + t) ^ ((r & 7) << 2);
    }
#pragma unroll
    for (int nt = 0; nt < 4; nt++) {
        const int r = n0 + nt * 8 + g;
        Db[nt] = (r * 32 + t) ^ ((r & 7) << 2);
    }

    float c[4][4][4];
#pragma unroll
    for (int i = 0; i < 4; i++)
#pragma unroll
        for (int j = 0; j < 4; j++)
#pragma unroll
            for (int q = 0; q < 4; q++) c[i][j][q] = 0.0f;

    // ---- preload chunk 0 into stage 0 ----
#pragma unroll
    for (int q = 0; q < 4; q++) {
        const int r = lr + 32 * q;
        cp16(smb + soff[q], Ag + (size_t)r * K + lc4 * 4);
        cp16(smb + 16384u + soff[q], Wg + (size_t)r * K + lc4 * 4);
    }
    CP_COMMIT();

    const int NCH = K >> 5;   // chunks of 32
    for (int ch = 0; ch < NCH; ch++) {
        CP_WAIT(0);           // chunk ch resident
        __syncthreads();      // all warps done with the other stage + see data

        // issue next chunk into the other stage (overlaps with MMAs below)
        if (ch + 1 < NCH) {
            const uint32_t sb = smb + (uint32_t)((ch + 1) & 1) * 32768u;
            const int kc = (ch + 1) * 32;
#pragma unroll
            for (int q = 0; q < 4; q++) {
                const int r = lr + 32 * q;
                cp16(sb + soff[q], Ag + (size_t)r * K + kc + lc4 * 4);
                cp16(sb + 16384u + soff[q], Wg + (size_t)r * K + kc + lc4 * 4);
            }
            CP_COMMIT();
        }

        const uint32_t* As = dsm + (ch & 1) * 8192;
        const uint32_t* Bs = As + 4096;
#pragma unroll
        for (int ks = 0; ks < 4; ks++) {
            const int kx0 = ks << 3;
            const int kx1 = kx0 | 4;
            uint32_t afr[4][4];
#pragma unroll
            for (int mt = 0; mt < 4; mt++) {
                afr[mt][0] = As[Da[mt][0] ^ kx0];
                afr[mt][1] = As[Da[mt][1] ^ kx0];
                afr[mt][2] = As[Da[mt][0] ^ kx1];
                afr[mt][3] = As[Da[mt][1] ^ kx1];
            }
            uint32_t bfr[4][2];
#pragma unroll
            for (int nt = 0; nt < 4; nt++) {
                bfr[nt][0] = Bs[Db[nt] ^ kx0];
                bfr[nt][1] = Bs[Db[nt] ^ kx1];
            }
#pragma unroll
            for (int mt = 0; mt < 4; mt++)
#pragma unroll
                for (int nt = 0; nt < 4; nt++)
                    mma_tf32(c[mt][nt], afr[mt], bfr[nt]);
        }
    }

    // ---- epilogue ----
#pragma unroll
    for (int mt = 0; mt < 4; mt++) {
#pragma unroll
        for (int half = 0; half < 2; half++) {
            const int m = bm + m0 + mt * 16 + g + half * 8;
#pragma unroll
            for (int nt = 0; nt < 4; nt++) {
                const int n = bn + n0 + nt * 8 + t * 2;
                const float v0 = c[mt][nt][half * 2 + 0] + bias[n + 0];
                const float v1 = c[mt][nt][half * 2 + 1] + bias[n + 1];
                if (EPI == 0) {
                    *(float2*)(C + (size_t)m * N + n) = make_float2(v0, v1);
                } else {
                    const int bb = m >> 11;
                    const int s  = m & 2047;
                    const int cg = n >> 10;
                    const int h  = (n & 1023) >> 6;
                    const int d  = n & 63;
                    const float sc = (cg == 0) ? 0.125f : 1.0f;
                    float* dst = (cg == 0) ? g_q : ((cg == 1) ? g_k : g_v);
                    float2 o = make_float2(tf32r(v0 * sc), tf32r(v1 * sc));
                    *(float2*)(dst + (((size_t)(bb * H_ + h)) * S_ + s) * DH_ + d) = o;
                }
            }
        }
    }
}

#define GEMM_SMEM (2 * 8192 * 4)   // 65536 B

// ---------------------------------------------------------------------------
// Flash attention on mma.sync tf32 (R5 structure; epilogue rounds ctx to tf32).
// CTA: 128 Q rows of one (b,h). 8 warps, warp = 16 rows. KV chunks of 64 keys.
// Smem (floats): Q[128][68], K[2][64][68], V[2][64][72]. Total 106,496 B.
// ---------------------------------------------------------------------------
#define QSTR 68
#define KSTR 68
#define VSTR 72
#define QS_OFF  0
#define KS_OFF  (128 * QSTR)                 // 8704
#define KS_SZ   (64 * KSTR)                  // 4352
#define VS_OFF  (KS_OFF + 2 * KS_SZ)         // 17408
#define VS_SZ   (64 * VSTR)                  // 4608
#define ATT_SMEM ((VS_OFF + 2 * VS_SZ) * 4)  // 106496 B

__global__ __launch_bounds__(256) void attn_mma(float* __restrict__ ctx)
{
    extern __shared__ float sm[];
    uint32_t* smu = (uint32_t*)sm;
    const uint32_t smb = smem_u32(sm);

    const int qb = (int)gridDim.x - 1 - (int)blockIdx.x;  // heavy tiles first
    const int bh = blockIdx.y;
    const int b  = bh >> 4;
    const int h  = bh & 15;
    const size_t base = (size_t)bh * (S_ * DH_);
    const int q0 = qb * 128;

    const int tid  = threadIdx.x;
    const int wid  = tid >> 5;
    const int lane = tid & 31;
    const int g = lane >> 2;
    const int t = lane & 3;

    // ---- async load Q tile + KV chunk 0 ----
#pragma unroll
    for (int it = 0; it < 8; it++) {
        const int idx = tid + 256 * it;
        const int r = idx >> 4, c4 = idx & 15;
        cp16(smb + (uint32_t)(QS_OFF + r * QSTR + c4 * 4) * 4,
             g_q + base + (size_t)(q0 + r) * DH_ + c4 * 4);
    }
#pragma unroll
    for (int it = 0; it < 4; it++) {
        const int idx = tid + 256 * it;
        const int r = idx >> 4, c4 = idx & 15;
        cp16(smb + (uint32_t)(KS_OFF + r * KSTR + c4 * 4) * 4,
             g_k + base + (size_t)r * DH_ + c4 * 4);
        cp16(smb + (uint32_t)(VS_OFF + r * VSTR + c4 * 4) * 4,
             g_v + base + (size_t)r * DH_ + c4 * 4);
    }
    CP_COMMIT();

    float o[8][4];
#pragma unroll
    for (int nt = 0; nt < 8; nt++)
#pragma unroll
        for (int j = 0; j < 4; j++) o[nt][j] = 0.0f;
    float m0r = -1e30f, m1r = -1e30f, l0r = 0.0f, l1r = 0.0f;

    const int nch = 2 * (qb + 1);
    const int aw = 16 * wid + g;

    for (int c = 0; c < nch; c++) {
        const int cb = c & 1;
        if (c + 1 < nch) {
            const int nb = (c + 1) & 1;
            const int koff = KS_OFF + nb * KS_SZ;
            const int voff = VS_OFF + nb * VS_SZ;
            const size_t kbase = base + (size_t)(c + 1) * 64 * DH_;
#pragma unroll
            for (int it = 0; it < 4; it++) {
                const int idx = tid + 256 * it;
                const int r = idx >> 4, c4 = idx & 15;
                cp16(smb + (uint32_t)(koff + r * KSTR + c4 * 4) * 4,
                     g_k + kbase + (size_t)r * DH_ + c4 * 4);
                cp16(smb + (uint32_t)(voff + r * VSTR + c4 * 4) * 4,
                     g_v + kbase + (size_t)r * DH_ + c4 * 4);
            }
            CP_COMMIT();
            CP_WAIT(1);
        } else {
            CP_WAIT(0);
        }
        __syncthreads();

        const int koff = KS_OFF + cb * KS_SZ;
        const int voff = VS_OFF + cb * VS_SZ;

        // ---- S = Q K^T ----
        float s[8][4];
#pragma unroll
        for (int nt = 0; nt < 8; nt++)
#pragma unroll
            for (int j = 0; j < 4; j++) s[nt][j] = 0.0f;

#pragma unroll
        for (int ks = 0; ks < 8; ks++) {
            const int kc = ks * 8;
            uint32_t a[4];
            a[0] = smu[aw * QSTR + kc + t];
            a[1] = smu[(aw + 8) * QSTR + kc + t];
            a[2] = smu[aw * QSTR + kc + 4 + t];
            a[3] = smu[(aw + 8) * QSTR + kc + 4 + t];
#pragma unroll
            for (int nt = 0; nt < 8; nt++) {
                uint32_t bfr[2];
                bfr[0] = smu[koff + (8 * nt + g) * KSTR + kc + t];
                bfr[1] = smu[koff + (8 * nt + g) * KSTR + kc + 4 + t];
                mma_tf32(s[nt], a, bfr);
            }
        }

        // ---- causal mask (diagonal chunks only) ----
        if (c * 64 + 63 > q0) {
            const int row0 = q0 + aw;
            const int row1 = row0 + 8;
            const int colb = c * 64 + 2 * t;
#pragma unroll
            for (int nt = 0; nt < 8; nt++) {
                const int col = colb + 8 * nt;
                if (col > row0)     s[nt][0] = -1e30f;
                if (col + 1 > row0) s[nt][1] = -1e30f;
                if (col > row1)     s[nt][2] = -1e30f;
                if (col + 1 > row1) s[nt][3] = -1e30f;
            }
        }

        // ---- online softmax ----
        float mn0 = -1e30f, mn1 = -1e30f;
#pragma unroll
        for (int nt = 0; nt < 8; nt++) {
            mn0 = fmaxf(mn0, fmaxf(s[nt][0], s[nt][1]));
            mn1 = fmaxf(mn1, fmaxf(s[nt][2], s[nt][3]));
        }
        mn0 = fmaxf(mn0, __shfl_xor_sync(0xffffffffu, mn0, 1));
        mn0 = fmaxf(mn0, __shfl_xor_sync(0xffffffffu, mn0, 2));
        mn1 = fmaxf(mn1, __shfl_xor_sync(0xffffffffu, mn1, 1));
        mn1 = fmaxf(mn1, __shfl_xor_sync(0xffffffffu, mn1, 2));
        const float mN0 = fmaxf(m0r, mn0);
        const float mN1 = fmaxf(m1r, mn1);
        const float sc0 = __expf(m0r - mN0);
        const float sc1 = __expf(m1r - mN1);
        m0r = mN0; m1r = mN1;

        float rs0 = 0.0f, rs1 = 0.0f;
#pragma unroll
        for (int nt = 0; nt < 8; nt++) {
            s[nt][0] = __expf(s[nt][0] - mN0); rs0 += s[nt][0];
            s[nt][1] = __expf(s[nt][1] - mN0); rs0 += s[nt][1];
            s[nt][2] = __expf(s[nt][2] - mN1); rs1 += s[nt][2];
            s[nt][3] = __expf(s[nt][3] - mN1); rs1 += s[nt][3];
        }
        rs0 += __shfl_xor_sync(0xffffffffu, rs0, 1);
        rs0 += __shfl_xor_sync(0xffffffffu, rs0, 2);
        rs1 += __shfl_xor_sync(0xffffffffu, rs1, 1);
        rs1 += __shfl_xor_sync(0xffffffffu, rs1, 2);
        l0r = l0r * sc0 + rs0;
        l1r = l1r * sc1 + rs1;
#pragma unroll
        for (int nt = 0; nt < 8; nt++) {
            o[nt][0] *= sc0; o[nt][1] *= sc0;
            o[nt][2] *= sc1; o[nt][3] *= sc1;
        }

        // ---- O += P V : C-layout -> A-fragment via quad shuffles ----
        const int qbase = lane & ~3;
        const int src0 = qbase + (t >> 1);
        const int src1 = src0 + 2;
#pragma unroll
        for (int ks = 0; ks < 8; ks++) {
            const uint32_t pc0 = f2tf32(s[ks][0]);
            const uint32_t pc1 = f2tf32(s[ks][1]);
            const uint32_t pc2 = f2tf32(s[ks][2]);
            const uint32_t pc3 = f2tf32(s[ks][3]);
            uint32_t a[4];
            {
                const uint32_t x0 = __shfl_sync(0xffffffffu, pc0, src0);
                const uint32_t x1 = __shfl_sync(0xffffffffu, pc1, src0);
                a[0] = (t & 1) ? x1 : x0;
                const uint32_t y0 = __shfl_sync(0xffffffffu, pc2, src0);
                const uint32_t y1 = __shfl_sync(0xffffffffu, pc3, src0);
                a[1] = (t & 1) ? y1 : y0;
                const uint32_t z0 = __shfl_sync(0xffffffffu, pc0, src1);
                const uint32_t z1 = __shfl_sync(0xffffffffu, pc1, src1);
                a[2] = (t & 1) ? z1 : z0;
                const uint32_t w0 = __shfl_sync(0xffffffffu, pc2, src1);
                const uint32_t w1 = __shfl_sync(0xffffffffu, pc3, src1);
                a[3] = (t & 1) ? w1 : w0;
            }
            const int kc = ks * 8;
#pragma unroll
            for (int nt = 0; nt < 8; nt++) {
                uint32_t bfr[2];
                bfr[0] = smu[voff + (kc + t) * VSTR + 8 * nt + g];
                bfr[1] = smu[voff + (kc + 4 + t) * VSTR + 8 * nt + g];
                mma_tf32(o[nt], a, bfr);
            }
        }
        __syncthreads();
    }

    // ---- epilogue (tf32-rounded for the out-proj GEMM) ----
    const float inv0 = 1.0f / l0r;
    const float inv1 = 1.0f / l1r;
    const int row0 = q0 + aw;
    float* dst0 = ctx + ((size_t)(b * S_) + row0) * D_ + h * DH_ + 2 * t;
    float* dst1 = dst0 + 8 * D_;
#pragma unroll
    for (int nt = 0; nt < 8; nt++) {
        *(float2*)(dst0 + 8 * nt) =
            make_float2(tf32r(o[nt][0] * inv0), tf32r(o[nt][1] * inv0));
        *(float2*)(dst1 + 8 * nt) =
            make_float2(tf32r(o[nt][2] * inv1), tf32r(o[nt][3] * inv1));
    }
}

// ---------------------------------------------------------------------------
extern "C" void kernel_launch(void* const* d_in, const int* in_sizes, int n_in,
                              void* d_out, int out_size)
{
    const float* x     = (const float*)d_in[0];
    // d_in[1] = mask (causal, implied) — unused
    const float* w_qkv = (const float*)d_in[2];
    const float* b_qkv = (const float*)d_in[3];
    const float* w_out = (const float*)d_in[4];
    const float* b_out = (const float*)d_in[5];
    float* out = (float*)d_out;

    float *ctx_ptr, *x_ptr, *wqkv_ptr, *wout_ptr;
    cudaGetSymbolAddress((void**)&ctx_ptr, g_ctx);
    cudaGetSymbolAddress((void**)&x_ptr, g_x);
    cudaGetSymbolAddress((void**)&wqkv_ptr, g_wqkv);
    cudaGetSymbolAddress((void**)&wout_ptr, g_wout);

    // 0) tf32 rounding pre-pass
    {
        const int n4x = M_ * D_ / 4;
        tf32_round_kernel<<<(n4x + 255) / 256, 256>>>(x, x_ptr, n4x);
        const int n4w = N_QKV * D_ / 4;
        tf32_round_kernel<<<(n4w + 255) / 256, 256>>>(w_qkv, wqkv_ptr, n4w);
        const int n4o = D_ * D_ / 4;
        tf32_round_kernel<<<(n4o + 255) / 256, 256>>>(w_out, wout_ptr, n4o);
    }

    // 1) QKV projection with scatter epilogue
    {
        cudaFuncSetAttribute(mma_gemm<1>,
                             cudaFuncAttributeMaxDynamicSharedMemorySize, GEMM_SMEM);
        dim3 grid(N_QKV / 128, M_ / 128);
        mma_gemm<1><<<grid, 256, GEMM_SMEM>>>(x_ptr, wqkv_ptr, b_qkv, nullptr,
                                              N_QKV, D_);
    }

    // 2) Causal flash attention
    {
        cudaFuncSetAttribute(attn_mma,
                             cudaFuncAttributeMaxDynamicSharedMemorySize, ATT_SMEM);
        dim3 grid(S_ / 128, B_ * H_);
        attn_mma<<<grid, 256, ATT_SMEM>>>(ctx_ptr);
    }

    // 3) Output projection
    {
        cudaFuncSetAttribute(mma_gemm<0>,
                             cudaFuncAttributeMaxDynamicSharedMemorySize, GEMM_SMEM);
        dim3 grid(D_ / 128, M_ / 128);
        mma_gemm<0><<<grid, 256, GEMM_SMEM>>>(ctx_ptr, wout_ptr, b_out, out, D_, D_);
    }
}

// round 8
// speedup vs baseline: 7.3941x; 1.9708x over previous
#include <cuda_runtime.h>
#include <cuda_fp16.h>
#include <cstdint>
#include <cstddef>

// Problem constants
#define B_ 4
#define S_ 2048
#define D_ 1024
#define H_ 16
#define DH_ 64
#define M_ (B_ * S_)      // 8192
#define N_QKV (3 * D_)    // 3072

// Scratch (device globals — no allocation allowed)
__device__ __half g_qh[(size_t)B_ * H_ * S_ * DH_];   // [B,H,S,Dh], Q pre-scaled 1/8
__device__ __half g_kh[(size_t)B_ * H_ * S_ * DH_];
__device__ __half g_vh[(size_t)B_ * H_ * S_ * DH_];
__device__ __half g_ctxh[(size_t)M_ * D_];            // [B,S,D]
__device__ __half g_xh[(size_t)M_ * D_];
__device__ __half g_wqkvh[(size_t)N_QKV * D_];
__device__ __half g_wouth[(size_t)D_ * D_];

// ---------------------------------------------------------------------------
// helpers
// ---------------------------------------------------------------------------
__device__ __forceinline__ void mma_f16(float* c, const uint32_t* a,
                                        const uint32_t* b) {
    asm volatile(
        "mma.sync.aligned.m16n8k16.row.col.f32.f16.f16.f32 "
        "{%0,%1,%2,%3}, {%4,%5,%6,%7}, {%8,%9}, {%0,%1,%2,%3};"
        : "+f"(c[0]), "+f"(c[1]), "+f"(c[2]), "+f"(c[3])
        : "r"(a[0]), "r"(a[1]), "r"(a[2]), "r"(a[3]), "r"(b[0]), "r"(b[1]));
}
__device__ __forceinline__ uint32_t smem_u32(const void* p) {
    uint32_t a;
    asm("{ .reg .u64 t; cvta.to.shared.u64 t, %1; cvt.u32.u64 %0, t; }"
        : "=r"(a) : "l"(p));
    return a;
}
__device__ __forceinline__ void cp16(uint32_t dst, const void* src) {
    asm volatile("cp.async.ca.shared.global [%0], [%1], 16;"
                 :: "r"(dst), "l"(src));
}
#define CP_COMMIT() asm volatile("cp.async.commit_group;" ::: "memory")
#define CP_WAIT(n)  asm volatile("cp.async.wait_group %0;" :: "n"(n) : "memory")

__device__ __forceinline__ uint32_t h2u(float lo, float hi) {
    __half2 h = __floats2half2_rn(lo, hi);
    return *(uint32_t*)&h;
}
__device__ __forceinline__ void ldsm_x2_trans(uint32_t& r0, uint32_t& r1,
                                              uint32_t addr) {
    asm volatile("ldmatrix.sync.aligned.m8n8.x2.trans.shared.b16 {%0,%1}, [%2];"
                 : "=r"(r0), "=r"(r1) : "r"(addr));
}

// ---------------------------------------------------------------------------
// fp32 -> fp16 pre-pass
// ---------------------------------------------------------------------------
__global__ void f2h_kernel(const float* __restrict__ src,
                           __half* __restrict__ dst, int n4)
{
    const int i = blockIdx.x * blockDim.x + threadIdx.x;
    if (i < n4) {
        float4 v = ((const float4*)src)[i];
        __half2* d = (__half2*)dst + 2 * i;
        d[0] = __floats2half2_rn(v.x, v.y);
        d[1] = __floats2half2_rn(v.z, v.w);
    }
}

// ---------------------------------------------------------------------------
// fp16 tensor-core GEMM: C[m,n] = sum_k A[m,k]*W[n,k] + bias[n]
// CTA tile 128x128, BK=64, 8 warps (2m x 4n), warp tile 64x32, m16n8k16.
// Smem rows padded to 72 halves (36 words) -> conflict-free LDS.32 fragments.
// 2-stage cp.async pipeline, 1 barrier/chunk, 2 CTAs/SM.
// Stage: A 128*36 + B 128*36 words = 36864 B; total 73728 B.
// EPI=0: f32 store to C.  EPI=1: scatter halves to g_qh/g_kh/g_vh (Q * 1/8).
// ---------------------------------------------------------------------------
#define RSTR 36   // words per padded row (72 halves)

template <int EPI>
__global__ __launch_bounds__(256, 2) void mma_gemm_h(
    const __half* __restrict__ A, const __half* __restrict__ W,
    const float* __restrict__ bias, float* __restrict__ C,
    int N, int K)
{
    extern __shared__ uint32_t dsm[];   // [2][9216] words
    const uint32_t smb = smem_u32(dsm);

    const int tid = threadIdx.x;
    const int wid = tid >> 5;
    const int lane = tid & 31;
    const int g = lane >> 2;
    const int t = lane & 3;
    const int m0 = (wid >> 2) * 64;
    const int n0 = (wid & 3) * 32;

    const int bm = blockIdx.y * 128;
    const int bn = blockIdx.x * 128;

    const __half* Ag = A + (size_t)bm * K;
    const __half* Wg = W + (size_t)bn * K;

    const int lr  = tid >> 3;     // loader row 0..31 (+32q)
    const int lc8 = tid & 7;      // 16B (8-half) group in 128B row
    uint32_t soff[4];
#pragma unroll
    for (int q = 0; q < 4; q++)
        soff[q] = (uint32_t)(lr + 32 * q) * (RSTR * 4) + lc8 * 16;

    // fragment base word offsets
    int Da[4][2], Db[4];
#pragma unroll
    for (int mt = 0; mt < 4; mt++) {
        Da[mt][0] = (m0 + mt * 16 + g) * RSTR + t;
        Da[mt][1] = (m0 + mt * 16 + g + 8) * RSTR + t;
    }
#pragma unroll
    for (int nt = 0; nt < 4; nt++)
        Db[nt] = (n0 + nt * 8 + g) * RSTR + t;

    float c[4][4][4];
#pragma unroll
    for (int i = 0; i < 4; i++)
#pragma unroll
        for (int j = 0; j < 4; j++)
#pragma unroll
            for (int q = 0; q < 4; q++) c[i][j][q] = 0.0f;

    // ---- preload chunk 0 into stage 0 ----
#pragma unroll
    for (int q = 0; q < 4; q++) {
        const int r = lr + 32 * q;
        cp16(smb + soff[q], Ag + (size_t)r * K + lc8 * 8);
        cp16(smb + 18432u + soff[q], Wg + (size_t)r * K + lc8 * 8);
    }
    CP_COMMIT();

    const int NCH = K >> 6;   // chunks of 64 k
    for (int ch = 0; ch < NCH; ch++) {
        CP_WAIT(0);
        __syncthreads();

        if (ch + 1 < NCH) {
            const uint32_t sb = smb + (uint32_t)((ch + 1) & 1) * 36864u;
            const int kc = (ch + 1) * 64;
#pragma unroll
            for (int q = 0; q < 4; q++) {
                const int r = lr + 32 * q;
                cp16(sb + soff[q], Ag + (size_t)r * K + kc + lc8 * 8);
                cp16(sb + 18432u + soff[q], Wg + (size_t)r * K + kc + lc8 * 8);
            }
            CP_COMMIT();
        }

        const uint32_t* As = dsm + (ch & 1) * 9216;
        const uint32_t* Bs = As + 4608;
#pragma unroll
        for (int ks = 0; ks < 4; ks++) {
            const int ko = ks * 8;
            uint32_t afr[4][4];
#pragma unroll
            for (int mt = 0; mt < 4; mt++) {
                afr[mt][0] = As[Da[mt][0] + ko];
                afr[mt][1] = As[Da[mt][1] + ko];
                afr[mt][2] = As[Da[mt][0] + ko + 4];
                afr[mt][3] = As[Da[mt][1] + ko + 4];
            }
            uint32_t bfr[4][2];
#pragma unroll
            for (int nt = 0; nt < 4; nt++) {
                bfr[nt][0] = Bs[Db[nt] + ko];
                bfr[nt][1] = Bs[Db[nt] + ko + 4];
            }
#pragma unroll
            for (int mt = 0; mt < 4; mt++)
#pragma unroll
                for (int nt = 0; nt < 4; nt++)
                    mma_f16(c[mt][nt], afr[mt], bfr[nt]);
        }
    }

    // ---- epilogue ----
#pragma unroll
    for (int mt = 0; mt < 4; mt++) {
#pragma unroll
        for (int half = 0; half < 2; half++) {
            const int m = bm + m0 + mt * 16 + g + half * 8;
#pragma unroll
            for (int nt = 0; nt < 4; nt++) {
                const int n = bn + n0 + nt * 8 + t * 2;
                const float v0 = c[mt][nt][half * 2 + 0] + bias[n + 0];
                const float v1 = c[mt][nt][half * 2 + 1] + bias[n + 1];
                if (EPI == 0) {
                    *(float2*)(C + (size_t)m * N + n) = make_float2(v0, v1);
                } else {
                    const int bb = m >> 11;
                    const int s  = m & 2047;
                    const int cg = n >> 10;
                    const int h  = (n & 1023) >> 6;
                    const int d  = n & 63;
                    const float sc = (cg == 0) ? 0.125f : 1.0f;
                    __half* dst = (cg == 0) ? g_qh : ((cg == 1) ? g_kh : g_vh);
                    __half2 o = __floats2half2_rn(v0 * sc, v1 * sc);
                    *(__half2*)(dst + (((size_t)(bb * H_ + h)) * S_ + s) * DH_ + d) = o;
                }
            }
        }
    }
}

#define GEMM_SMEM (2 * 9216 * 4)   // 73728 B

// ---------------------------------------------------------------------------
// fp16 flash attention. CTA: 128 Q rows, 8 warps x 16 rows, 64-key chunks.
// Q in registers (16 u32, loaded from gmem). K/V double-buffered smem,
// rows padded to 72 halves. P C-frag packs directly into PV A-frag (no
// shuffles). V read via ldmatrix.x2.trans. Smem: (2+2)*64*36 words = 36 KB.
// ---------------------------------------------------------------------------
#define AKS_SZ  (64 * RSTR)                 // 2304 words per K stage
#define AVS_OFF (2 * AKS_SZ)                // 4608
#define ATT_SMEM ((4 * AKS_SZ) * 4)         // 36864 B

__global__ __launch_bounds__(256, 2) void attn_mma_h(__half* __restrict__ ctx)
{
    extern __shared__ uint32_t smw[];
    const uint32_t smb = smem_u32(smw);

    const int qb = (int)gridDim.x - 1 - (int)blockIdx.x;  // heavy tiles first
    const int bh = blockIdx.y;
    const int b  = bh >> 4;
    const int h  = bh & 15;
    const size_t base = (size_t)bh * (S_ * DH_);
    const int q0 = qb * 128;

    const int tid  = threadIdx.x;
    const int wid  = tid >> 5;
    const int lane = tid & 31;
    const int g = lane >> 2;
    const int t = lane & 3;
    const int aw = 16 * wid + g;
    const int row0 = q0 + aw;

    // loaders: K/V tile = 64 rows x 8 groups = 512 cp16; 2 per thread per tile
    const int lr  = tid >> 3;      // 0..31 (+32)
    const int lc8 = tid & 7;
    uint32_t soff[2];
#pragma unroll
    for (int q = 0; q < 2; q++)
        soff[q] = (uint32_t)(lr + 32 * q) * (RSTR * 4) + lc8 * 16;

    // ---- async load K/V chunk 0 ----
#pragma unroll
    for (int q = 0; q < 2; q++) {
        const int r = lr + 32 * q;
        cp16(smb + soff[q], g_kh + base + (size_t)r * DH_ + lc8 * 8);
        cp16(smb + AVS_OFF * 4 + soff[q], g_vh + base + (size_t)r * DH_ + lc8 * 8);
    }
    CP_COMMIT();

    // ---- Q fragments in registers (overlaps with cp.async) ----
    uint32_t qa[4][4];
    {
        const __half* qp = g_qh + base + (size_t)row0 * DH_ + 2 * t;
        const __half* qp8 = qp + 8 * DH_;
#pragma unroll
        for (int ks = 0; ks < 4; ks++) {
            qa[ks][0] = *(const uint32_t*)(qp + ks * 16);
            qa[ks][1] = *(const uint32_t*)(qp8 + ks * 16);
            qa[ks][2] = *(const uint32_t*)(qp + ks * 16 + 8);
            qa[ks][3] = *(const uint32_t*)(qp8 + ks * 16 + 8);
        }
    }

    float o[8][4];
#pragma unroll
    for (int nt = 0; nt < 8; nt++)
#pragma unroll
        for (int j = 0; j < 4; j++) o[nt][j] = 0.0f;
    float m0r = -1e30f, m1r = -1e30f, l0r = 0.0f, l1r = 0.0f;

    // fragment bases
    int Dk[8];
#pragma unroll
    for (int nt = 0; nt < 8; nt++)
        Dk[nt] = (8 * nt + g) * RSTR + t;
    const uint32_t vrow = (uint32_t)(lane & 15) * (RSTR * 4);

    const int nch = 2 * (qb + 1);
    for (int c = 0; c < nch; c++) {
        const int cb = c & 1;
        if (c + 1 < nch) {
            const int nb = (c + 1) & 1;
            const size_t kbase = base + (size_t)(c + 1) * 64 * DH_;
            const uint32_t kd = smb + (uint32_t)nb * (AKS_SZ * 4);
            const uint32_t vd = smb + (uint32_t)(AVS_OFF + nb * AKS_SZ) * 4;
#pragma unroll
            for (int q = 0; q < 2; q++) {
                const int r = lr + 32 * q;
                cp16(kd + soff[q], g_kh + kbase + (size_t)r * DH_ + lc8 * 8);
                cp16(vd + soff[q], g_vh + kbase + (size_t)r * DH_ + lc8 * 8);
            }
            CP_COMMIT();
            CP_WAIT(1);
        } else {
            CP_WAIT(0);
        }
        __syncthreads();

        const uint32_t* Ks = smw + cb * AKS_SZ;
        const uint32_t vsb = smb + (uint32_t)(AVS_OFF + cb * AKS_SZ) * 4;

        // ---- S = Q K^T ----
        float s[8][4];
#pragma unroll
        for (int nt = 0; nt < 8; nt++)
#pragma unroll
            for (int j = 0; j < 4; j++) s[nt][j] = 0.0f;

#pragma unroll
        for (int ks = 0; ks < 4; ks++) {
            const int ko = ks * 8;
#pragma unroll
            for (int nt = 0; nt < 8; nt++) {
                uint32_t bfr[2];
                bfr[0] = Ks[Dk[nt] + ko];
                bfr[1] = Ks[Dk[nt] + ko + 4];
                mma_f16(s[nt], qa[ks], bfr);
            }
        }

        // ---- causal mask (diagonal chunks only) ----
        if (c * 64 + 63 > q0) {
            const int r1 = row0 + 8;
            const int colb = c * 64 + 2 * t;
#pragma unroll
            for (int nt = 0; nt < 8; nt++) {
                const int col = colb + 8 * nt;
                if (col > row0)     s[nt][0] = -1e30f;
                if (col + 1 > row0) s[nt][1] = -1e30f;
                if (col > r1)       s[nt][2] = -1e30f;
                if (col + 1 > r1)   s[nt][3] = -1e30f;
            }
        }

        // ---- online softmax ----
        float mn0 = -1e30f, mn1 = -1e30f;
#pragma unroll
        for (int nt = 0; nt < 8; nt++) {
            mn0 = fmaxf(mn0, fmaxf(s[nt][0], s[nt][1]));
            mn1 = fmaxf(mn1, fmaxf(s[nt][2], s[nt][3]));
        }
        mn0 = fmaxf(mn0, __shfl_xor_sync(0xffffffffu, mn0, 1));
        mn0 = fmaxf(mn0, __shfl_xor_sync(0xffffffffu, mn0, 2));
        mn1 = fmaxf(mn1, __shfl_xor_sync(0xffffffffu, mn1, 1));
        mn1 = fmaxf(mn1, __shfl_xor_sync(0xffffffffu, mn1, 2));
        const float mN0 = fmaxf(m0r, mn0);
        const float mN1 = fmaxf(m1r, mn1);
        const float sc0 = __expf(m0r - mN0);
        const float sc1 = __expf(m1r - mN1);
        m0r = mN0; m1r = mN1;

        float rs0 = 0.0f, rs1 = 0.0f;
#pragma unroll
        for (int nt = 0; nt < 8; nt++) {
            s[nt][0] = __expf(s[nt][0] - mN0); rs0 += s[nt][0];
            s[nt][1] = __expf(s[nt][1] - mN0); rs0 += s[nt][1];
            s[nt][2] = __expf(s[nt][2] - mN1); rs1 += s[nt][2];
            s[nt][3] = __expf(s[nt][3] - mN1); rs1 += s[nt][3];
        }
        rs0 += __shfl_xor_sync(0xffffffffu, rs0, 1);
        rs0 += __shfl_xor_sync(0xffffffffu, rs0, 2);
        rs1 += __shfl_xor_sync(0xffffffffu, rs1, 1);
        rs1 += __shfl_xor_sync(0xffffffffu, rs1, 2);
        l0r = l0r * sc0 + rs0;
        l1r = l1r * sc1 + rs1;
#pragma unroll
        for (int nt = 0; nt < 8; nt++) {
            o[nt][0] *= sc0; o[nt][1] *= sc0;
            o[nt][2] *= sc1; o[nt][3] *= sc1;
        }

        // ---- O += P V ----
#pragma unroll
        for (int ks = 0; ks < 4; ks++) {
            uint32_t a[4];
            a[0] = h2u(s[2 * ks][0],     s[2 * ks][1]);
            a[1] = h2u(s[2 * ks][2],     s[2 * ks][3]);
            a[2] = h2u(s[2 * ks + 1][0], s[2 * ks + 1][1]);
            a[3] = h2u(s[2 * ks + 1][2], s[2 * ks + 1][3]);
            const uint32_t vk = vsb + (uint32_t)(ks * 16) * (RSTR * 4) + vrow;
#pragma unroll
            for (int nt = 0; nt < 8; nt++) {
                uint32_t b0, b1;
                ldsm_x2_trans(b0, b1, vk + nt * 16);
                uint32_t bfr[2] = {b0, b1};
                mma_f16(o[nt], a, bfr);
            }
        }
        __syncthreads();
    }

    // ---- epilogue: ctx halves ----
    const float inv0 = 1.0f / l0r;
    const float inv1 = 1.0f / l1r;
    __half* dst0 = ctx + ((size_t)(b * S_) + row0) * D_ + h * DH_ + 2 * t;
    __half* dst1 = dst0 + 8 * D_;
#pragma unroll
    for (int nt = 0; nt < 8; nt++) {
        *(__half2*)(dst0 + 8 * nt) = __floats2half2_rn(o[nt][0] * inv0, o[nt][1] * inv0);
        *(__half2*)(dst1 + 8 * nt) = __floats2half2_rn(o[nt][2] * inv1, o[nt][3] * inv1);
    }
}

// ---------------------------------------------------------------------------
extern "C" void kernel_launch(void* const* d_in, const int* in_sizes, int n_in,
                              void* d_out, int out_size)
{
    const float* x     = (const float*)d_in[0];
    // d_in[1] = mask (causal, implied) — unused
    const float* w_qkv = (const float*)d_in[2];
    const float* b_qkv = (const float*)d_in[3];
    const float* w_out = (const float*)d_in[4];
    const float* b_out = (const float*)d_in[5];
    float* out = (float*)d_out;

    __half *ctx_ptr, *x_ptr, *wqkv_ptr, *wout_ptr;
    cudaGetSymbolAddress((void**)&ctx_ptr, g_ctxh);
    cudaGetSymbolAddress((void**)&x_ptr, g_xh);
    cudaGetSymbolAddress((void**)&wqkv_ptr, g_wqkvh);
    cudaGetSymbolAddress((void**)&wout_ptr, g_wouth);

    // 0) fp16 conversion pre-pass
    {
        const int n4x = M_ * D_ / 4;
        f2h_kernel<<<(n4x + 255) / 256, 256>>>(x, x_ptr, n4x);
        const int n4w = N_QKV * D_ / 4;
        f2h_kernel<<<(n4w + 255) / 256, 256>>>(w_qkv, wqkv_ptr, n4w);
        const int n4o = D_ * D_ / 4;
        f2h_kernel<<<(n4o + 255) / 256, 256>>>(w_out, wout_ptr, n4o);
    }

    // 1) QKV projection with scatter epilogue
    {
        cudaFuncSetAttribute(mma_gemm_h<1>,
                             cudaFuncAttributeMaxDynamicSharedMemorySize, GEMM_SMEM);
        dim3 grid(N_QKV / 128, M_ / 128);
        mma_gemm_h<1><<<grid, 256, GEMM_SMEM>>>(x_ptr, wqkv_ptr, b_qkv, nullptr,
                                                N_QKV, D_);
    }

    // 2) Causal flash attention (fp16 mma)
    {
        cudaFuncSetAttribute(attn_mma_h,
                             cudaFuncAttributeMaxDynamicSharedMemorySize, ATT_SMEM);
        dim3 grid(S_ / 128, B_ * H_);
        attn_mma_h<<<grid, 256, ATT_SMEM>>>(ctx_ptr);
    }

    // 3) Output projection
    {
        cudaFuncSetAttribute(mma_gemm_h<0>,
                             cudaFuncAttributeMaxDynamicSharedMemorySize, GEMM_SMEM);
        dim3 grid(D_ / 128, M_ / 128);
        mma_gemm_h<0><<<grid, 256, GEMM_SMEM>>>(ctx_ptr, wout_ptr, b_out, out,
                                                D_, D_);
    }
}

// round 9
// speedup vs baseline: 7.9000x; 1.0684x over previous
#include <cuda_runtime.h>
#include <cuda_fp16.h>
#include <cstdint>
#include <cstddef>

// Problem constants
#define B_ 4
#define S_ 2048
#define D_ 1024
#define H_ 16
#define DH_ 64
#define M_ (B_ * S_)      // 8192
#define N_QKV (3 * D_)    // 3072

// Scratch (device globals — no allocation allowed)
__device__ __half g_qh[(size_t)B_ * H_ * S_ * DH_];   // [B,H,S,Dh], Q pre-scaled 1/8
__device__ __half g_kh[(size_t)B_ * H_ * S_ * DH_];
__device__ __half g_vh[(size_t)B_ * H_ * S_ * DH_];
__device__ __half g_ctxh[(size_t)M_ * D_];            // [B,S,D]
__device__ __half g_xh[(size_t)M_ * D_];
__device__ __half g_wqkvh[(size_t)N_QKV * D_];
__device__ __half g_wouth[(size_t)D_ * D_];

// ---------------------------------------------------------------------------
// helpers
// ---------------------------------------------------------------------------
__device__ __forceinline__ void mma_f16(float* c, const uint32_t* a,
                                        const uint32_t* b) {
    asm volatile(
        "mma.sync.aligned.m16n8k16.row.col.f32.f16.f16.f32 "
        "{%0,%1,%2,%3}, {%4,%5,%6,%7}, {%8,%9}, {%0,%1,%2,%3};"
        : "+f"(c[0]), "+f"(c[1]), "+f"(c[2]), "+f"(c[3])
        : "r"(a[0]), "r"(a[1]), "r"(a[2]), "r"(a[3]), "r"(b[0]), "r"(b[1]));
}
__device__ __forceinline__ uint32_t smem_u32(const void* p) {
    uint32_t a;
    asm("{ .reg .u64 t; cvta.to.shared.u64 t, %1; cvt.u32.u64 %0, t; }"
        : "=r"(a) : "l"(p));
    return a;
}
__device__ __forceinline__ void cp16(uint32_t dst, const void* src) {
    asm volatile("cp.async.ca.shared.global [%0], [%1], 16;"
                 :: "r"(dst), "l"(src));
}
#define CP_COMMIT() asm volatile("cp.async.commit_group;" ::: "memory")
#define CP_WAIT(n)  asm volatile("cp.async.wait_group %0;" :: "n"(n) : "memory")

__device__ __forceinline__ uint32_t h2u(float lo, float hi) {
    __half2 h = __floats2half2_rn(lo, hi);
    return *(uint32_t*)&h;
}
__device__ __forceinline__ void ldsm_x4(uint32_t& r0, uint32_t& r1,
                                        uint32_t& r2, uint32_t& r3,
                                        uint32_t addr) {
    asm volatile("ldmatrix.sync.aligned.m8n8.x4.shared.b16 {%0,%1,%2,%3}, [%4];"
                 : "=r"(r0), "=r"(r1), "=r"(r2), "=r"(r3) : "r"(addr));
}
__device__ __forceinline__ void ldsm_x2_trans(uint32_t& r0, uint32_t& r1,
                                              uint32_t addr) {
    asm volatile("ldmatrix.sync.aligned.m8n8.x2.trans.shared.b16 {%0,%1}, [%2];"
                 : "=r"(r0), "=r"(r1) : "r"(addr));
}

// ---------------------------------------------------------------------------
// fp32 -> fp16 pre-pass
// ---------------------------------------------------------------------------
__global__ void f2h_kernel(const float* __restrict__ src,
                           __half* __restrict__ dst, int n4)
{
    const int i = blockIdx.x * blockDim.x + threadIdx.x;
    if (i < n4) {
        float4 v = ((const float4*)src)[i];
        __half2* d = (__half2*)dst + 2 * i;
        d[0] = __floats2half2_rn(v.x, v.y);
        d[1] = __floats2half2_rn(v.z, v.w);
    }
}

// ---------------------------------------------------------------------------
// fp16 tensor-core GEMM: C[m,n] = sum_k A[m,k]*W[n,k] + bias[n]
// CTA 128x128, BK=64, 8 warps (2m x 4n), warp tile 64x32, m16n8k16.
// Fragments via ldmatrix.x4 (rows padded to 72 halves -> conflict-free).
// 2-stage cp.async pipeline, 1 barrier/chunk, 2 CTAs/SM.
// ---------------------------------------------------------------------------
#define RSTR 36           // words per padded row (72 halves = 144 B)
#define STAGE_B 36864u    // bytes per stage (A 18432 + B 18432)

template <int EPI>
__global__ __launch_bounds__(256, 2) void mma_gemm_h(
    const __half* __restrict__ A, const __half* __restrict__ W,
    const float* __restrict__ bias, float* __restrict__ C,
    int N, int K)
{
    extern __shared__ uint32_t dsm[];
    const uint32_t smb = smem_u32(dsm);

    const int tid = threadIdx.x;
    const int wid = tid >> 5;
    const int lane = tid & 31;
    const int g = lane >> 2;
    const int t = lane & 3;
    const int m0 = (wid >> 2) * 64;
    const int n0 = (wid & 3) * 32;

    const int bm = blockIdx.y * 128;
    const int bn = blockIdx.x * 128;

    const __half* Ag = A + (size_t)bm * K;
    const __half* Wg = W + (size_t)bn * K;

    const int lr  = tid >> 3;     // loader row 0..31 (+32q)
    const int lc8 = tid & 7;      // 16B (8-half) group in 128B row
    uint32_t soff[4];
#pragma unroll
    for (int q = 0; q < 4; q++)
        soff[q] = (uint32_t)(lr + 32 * q) * (RSTR * 4) + lc8 * 16;

    // ldmatrix per-lane base addresses (stage 0)
    // A x4 for m-tile mt: matrices {rowblk, rowblk+8} x {klo, khi}
    uint32_t aAddr[4];
#pragma unroll
    for (int mt = 0; mt < 4; mt++) {
        const int row = m0 + mt * 16 + (lane & 7) + ((lane >> 3) & 1) * 8;
        aAddr[mt] = smb + (uint32_t)row * (RSTR * 4) + ((lane >> 4) * 16);
    }
    // B x4 for n-pair p: matrices {nt=2p,b0},{2p,b1},{2p+1,b0},{2p+1,b1}
    uint32_t bAddr[2];
#pragma unroll
    for (int p = 0; p < 2; p++) {
        const int row = n0 + p * 16 + ((lane >> 4) * 8) + (lane & 7);
        bAddr[p] = smb + 18432u + (uint32_t)row * (RSTR * 4) +
                   (((lane >> 3) & 1) * 16);
    }

    float c[4][4][4];
#pragma unroll
    for (int i = 0; i < 4; i++)
#pragma unroll
        for (int j = 0; j < 4; j++)
#pragma unroll
            for (int q = 0; q < 4; q++) c[i][j][q] = 0.0f;

    // ---- preload chunk 0 into stage 0 ----
#pragma unroll
    for (int q = 0; q < 4; q++) {
        const int r = lr + 32 * q;
        cp16(smb + soff[q], Ag + (size_t)r * K + lc8 * 8);
        cp16(smb + 18432u + soff[q], Wg + (size_t)r * K + lc8 * 8);
    }
    CP_COMMIT();

    const int NCH = K >> 6;
    for (int ch = 0; ch < NCH; ch++) {
        CP_WAIT(0);
        __syncthreads();

        if (ch + 1 < NCH) {
            const uint32_t sb = smb + (uint32_t)((ch + 1) & 1) * STAGE_B;
            const int kc = (ch + 1) * 64;
#pragma unroll
            for (int q = 0; q < 4; q++) {
                const int r = lr + 32 * q;
                cp16(sb + soff[q], Ag + (size_t)r * K + kc + lc8 * 8);
                cp16(sb + 18432u + soff[q], Wg + (size_t)r * K + kc + lc8 * 8);
            }
            CP_COMMIT();
        }

        const uint32_t st = (uint32_t)(ch & 1) * STAGE_B;
#pragma unroll
        for (int ks = 0; ks < 4; ks++) {
            const uint32_t ko = st + (uint32_t)ks * 32;
            uint32_t afr[4][4];
#pragma unroll
            for (int mt = 0; mt < 4; mt++)
                ldsm_x4(afr[mt][0], afr[mt][1], afr[mt][2], afr[mt][3],
                        aAddr[mt] + ko);
            uint32_t bq[2][4];
#pragma unroll
            for (int p = 0; p < 2; p++)
                ldsm_x4(bq[p][0], bq[p][1], bq[p][2], bq[p][3], bAddr[p] + ko);
#pragma unroll
            for (int mt = 0; mt < 4; mt++)
#pragma unroll
                for (int nt = 0; nt < 4; nt++) {
                    uint32_t bfr[2] = {bq[nt >> 1][(nt & 1) * 2],
                                       bq[nt >> 1][(nt & 1) * 2 + 1]};
                    mma_f16(c[mt][nt], afr[mt], bfr);
                }
        }
    }

    // ---- epilogue ----
#pragma unroll
    for (int mt = 0; mt < 4; mt++) {
#pragma unroll
        for (int half = 0; half < 2; half++) {
            const int m = bm + m0 + mt * 16 + g + half * 8;
#pragma unroll
            for (int nt = 0; nt < 4; nt++) {
                const int n = bn + n0 + nt * 8 + t * 2;
                const float v0 = c[mt][nt][half * 2 + 0] + bias[n + 0];
                const float v1 = c[mt][nt][half * 2 + 1] + bias[n + 1];
                if (EPI == 0) {
                    *(float2*)(C + (size_t)m * N + n) = make_float2(v0, v1);
                } else {
                    const int bb = m >> 11;
                    const int s  = m & 2047;
                    const int cg = n >> 10;
                    const int h  = (n & 1023) >> 6;
                    const int d  = n & 63;
                    const float sc = (cg == 0) ? 0.125f : 1.0f;
                    __half* dst = (cg == 0) ? g_qh : ((cg == 1) ? g_kh : g_vh);
                    __half2 o = __floats2half2_rn(v0 * sc, v1 * sc);
                    *(__half2*)(dst + (((size_t)(bb * H_ + h)) * S_ + s) * DH_ + d) = o;
                }
            }
        }
    }
}

#define GEMM_SMEM (2 * 9216 * 4)   // 73728 B

// ---------------------------------------------------------------------------
// fp16 flash attention. CTA: 128 Q rows, 8 warps x 16 rows, 64-key chunks.
// Q in registers; K frags via ldmatrix.x4; V via ldmatrix.x2.trans.
// K/V double-buffered smem, rows padded to 72 halves. Smem 36 KB, 2 CTAs/SM.
// ---------------------------------------------------------------------------
#define AKS_SZ  (64 * RSTR)                 // 2304 words per K stage
#define AVS_OFF (2 * AKS_SZ)                // 4608
#define ATT_SMEM ((4 * AKS_SZ) * 4)         // 36864 B

__global__ __launch_bounds__(256, 2) void attn_mma_h(__half* __restrict__ ctx)
{
    extern __shared__ uint32_t smw[];
    const uint32_t smb = smem_u32(smw);

    const int qb = (int)gridDim.x - 1 - (int)blockIdx.x;  // heavy tiles first
    const int bh = blockIdx.y;
    const int b  = bh >> 4;
    const int h  = bh & 15;
    const size_t base = (size_t)bh * (S_ * DH_);
    const int q0 = qb * 128;

    const int tid  = threadIdx.x;
    const int wid  = tid >> 5;
    const int lane = tid & 31;
    const int g = lane >> 2;
    const int t = lane & 3;
    const int aw = 16 * wid + g;
    const int row0 = q0 + aw;

    const int lr  = tid >> 3;      // 0..31 (+32)
    const int lc8 = tid & 7;
    uint32_t soff[2];
#pragma unroll
    for (int q = 0; q < 2; q++)
        soff[q] = (uint32_t)(lr + 32 * q) * (RSTR * 4) + lc8 * 16;

    // ---- async load K/V chunk 0 ----
#pragma unroll
    for (int q = 0; q < 2; q++) {
        const int r = lr + 32 * q;
        cp16(smb + soff[q], g_kh + base + (size_t)r * DH_ + lc8 * 8);
        cp16(smb + AVS_OFF * 4 + soff[q], g_vh + base + (size_t)r * DH_ + lc8 * 8);
    }
    CP_COMMIT();

    // ---- Q fragments in registers ----
    uint32_t qa[4][4];
    {
        const __half* qp = g_qh + base + (size_t)row0 * DH_ + 2 * t;
        const __half* qp8 = qp + 8 * DH_;
#pragma unroll
        for (int ks = 0; ks < 4; ks++) {
            qa[ks][0] = *(const uint32_t*)(qp + ks * 16);
            qa[ks][1] = *(const uint32_t*)(qp8 + ks * 16);
            qa[ks][2] = *(const uint32_t*)(qp + ks * 16 + 8);
            qa[ks][3] = *(const uint32_t*)(qp8 + ks * 16 + 8);
        }
    }

    // ldmatrix per-lane K base addresses: pair p covers nt=2p,2p+1
    uint32_t kAddr[4];
#pragma unroll
    for (int p = 0; p < 4; p++) {
        const int row = p * 16 + ((lane >> 4) * 8) + (lane & 7);
        kAddr[p] = smb + (uint32_t)row * (RSTR * 4) + (((lane >> 3) & 1) * 16);
    }
    const uint32_t vrow = (uint32_t)(lane & 15) * (RSTR * 4);

    float o[8][4];
#pragma unroll
    for (int nt = 0; nt < 8; nt++)
#pragma unroll
        for (int j = 0; j < 4; j++) o[nt][j] = 0.0f;
    float m0r = -1e30f, m1r = -1e30f, l0r = 0.0f, l1r = 0.0f;

    const int nch = 2 * (qb + 1);
    for (int c = 0; c < nch; c++) {
        const int cb = c & 1;
        if (c + 1 < nch) {
            const int nb = (c + 1) & 1;
            const size_t kbase = base + (size_t)(c + 1) * 64 * DH_;
            const uint32_t kd = smb + (uint32_t)nb * (AKS_SZ * 4);
            const uint32_t vd = smb + (uint32_t)(AVS_OFF + nb * AKS_SZ) * 4;
#pragma unroll
            for (int q = 0; q < 2; q++) {
                const int r = lr + 32 * q;
                cp16(kd + soff[q], g_kh + kbase + (size_t)r * DH_ + lc8 * 8);
                cp16(vd + soff[q], g_vh + kbase + (size_t)r * DH_ + lc8 * 8);
            }
            CP_COMMIT();
            CP_WAIT(1);
        } else {
            CP_WAIT(0);
        }
        __syncthreads();

        const uint32_t kst = (uint32_t)cb * (AKS_SZ * 4);
        const uint32_t vsb = smb + (uint32_t)(AVS_OFF + cb * AKS_SZ) * 4;

        // ---- S = Q K^T ----
        float s[8][4];
#pragma unroll
        for (int nt = 0; nt < 8; nt++)
#pragma unroll
            for (int j = 0; j < 4; j++) s[nt][j] = 0.0f;

#pragma unroll
        for (int ks = 0; ks < 4; ks++) {
            const uint32_t ko = kst + (uint32_t)ks * 32;
#pragma unroll
            for (int p = 0; p < 4; p++) {
                uint32_t kq[4];
                ldsm_x4(kq[0], kq[1], kq[2], kq[3], kAddr[p] + ko);
                {
                    uint32_t bfr[2] = {kq[0], kq[1]};
                    mma_f16(s[2 * p], qa[ks], bfr);
                }
                {
                    uint32_t bfr[2] = {kq[2], kq[3]};
                    mma_f16(s[2 * p + 1], qa[ks], bfr);
                }
            }
        }

        // ---- causal mask (diagonal chunks only) ----
        if (c * 64 + 63 > q0) {
            const int r1 = row0 + 8;
            const int colb = c * 64 + 2 * t;
#pragma unroll
            for (int nt = 0; nt < 8; nt++) {
                const int col = colb + 8 * nt;
                if (col > row0)     s[nt][0] = -1e30f;
                if (col + 1 > row0) s[nt][1] = -1e30f;
                if (col > r1)       s[nt][2] = -1e30f;
                if (col + 1 > r1)   s[nt][3] = -1e30f;
            }
        }

        // ---- online softmax ----
        float mn0 = -1e30f, mn1 = -1e30f;
#pragma unroll
        for (int nt = 0; nt < 8; nt++) {
            mn0 = fmaxf(mn0, fmaxf(s[nt][0], s[nt][1]));
            mn1 = fmaxf(mn1, fmaxf(s[nt][2], s[nt][3]));
        }
        mn0 = fmaxf(mn0, __shfl_xor_sync(0xffffffffu, mn0, 1));
        mn0 = fmaxf(mn0, __shfl_xor_sync(0xffffffffu, mn0, 2));
        mn1 = fmaxf(mn1, __shfl_xor_sync(0xffffffffu, mn1, 1));
        mn1 = fmaxf(mn1, __shfl_xor_sync(0xffffffffu, mn1, 2));
        const float mN0 = fmaxf(m0r, mn0);
        const float mN1 = fmaxf(m1r, mn1);
        const float sc0 = __expf(m0r - mN0);
        const float sc1 = __expf(m1r - mN1);
        m0r = mN0; m1r = mN1;

        float rs0 = 0.0f, rs1 = 0.0f;
#pragma unroll
        for (int nt = 0; nt < 8; nt++) {
            s[nt][0] = __expf(s[nt][0] - mN0); rs0 += s[nt][0];
            s[nt][1] = __expf(s[nt][1] - mN0); rs0 += s[nt][1];
            s[nt][2] = __expf(s[nt][2] - mN1); rs1 += s[nt][2];
            s[nt][3] = __expf(s[nt][3] - mN1); rs1 += s[nt][3];
        }
        rs0 += __shfl_xor_sync(0xffffffffu, rs0, 1);
        rs0 += __shfl_xor_sync(0xffffffffu, rs0, 2);
        rs1 += __shfl_xor_sync(0xffffffffu, rs1, 1);
        rs1 += __shfl_xor_sync(0xffffffffu, rs1, 2);
        l0r = l0r * sc0 + rs0;
        l1r = l1r * sc1 + rs1;
#pragma unroll
        for (int nt = 0; nt < 8; nt++) {
            o[nt][0] *= sc0; o[nt][1] *= sc0;
            o[nt][2] *= sc1; o[nt][3] *= sc1;
        }

        // ---- O += P V ----
#pragma unroll
        for (int ks = 0; ks < 4; ks++) {
            uint32_t a[4];
            a[0] = h2u(s[2 * ks][0],     s[2 * ks][1]);
            a[1] = h2u(s[2 * ks][2],     s[2 * ks][3]);
            a[2] = h2u(s[2 * ks + 1][0], s[2 * ks + 1][1]);
            a[3] = h2u(s[2 * ks + 1][2], s[2 * ks + 1][3]);
            const uint32_t vk = vsb + (uint32_t)(ks * 16) * (RSTR * 4) + vrow;
#pragma unroll
            for (int nt = 0; nt < 8; nt++) {
                uint32_t b0, b1;
                ldsm_x2_trans(b0, b1, vk + nt * 16);
                uint32_t bfr[2] = {b0, b1};
                mma_f16(o[nt], a, bfr);
            }
        }
        __syncthreads();
    }

    // ---- epilogue: ctx halves ----
    const float inv0 = 1.0f / l0r;
    const float inv1 = 1.0f / l1r;
    __half* dst0 = ctx + ((size_t)(b * S_) + row0) * D_ + h * DH_ + 2 * t;
    __half* dst1 = dst0 + 8 * D_;
#pragma unroll
    for (int nt = 0; nt < 8; nt++) {
        *(__half2*)(dst0 + 8 * nt) = __floats2half2_rn(o[nt][0] * inv0, o[nt][1] * inv0);
        *(__half2*)(dst1 + 8 * nt) = __floats2half2_rn(o[nt][2] * inv1, o[nt][3] * inv1);
    }
}

// ---------------------------------------------------------------------------
extern "C" void kernel_launch(void* const* d_in, const int* in_sizes, int n_in,
                              void* d_out, int out_size)
{
    const float* x     = (const float*)d_in[0];
    // d_in[1] = mask (causal, implied) — unused
    const float* w_qkv = (const float*)d_in[2];
    const float* b_qkv = (const float*)d_in[3];
    const float* w_out = (const float*)d_in[4];
    const float* b_out = (const float*)d_in[5];
    float* out = (float*)d_out;

    __half *ctx_ptr, *x_ptr, *wqkv_ptr, *wout_ptr;
    cudaGetSymbolAddress((void**)&ctx_ptr, g_ctxh);
    cudaGetSymbolAddress((void**)&x_ptr, g_xh);
    cudaGetSymbolAddress((void**)&wqkv_ptr, g_wqkvh);
    cudaGetSymbolAddress((void**)&wout_ptr, g_wouth);

    // 0) fp16 conversion pre-pass
    {
        const int n4x = M_ * D_ / 4;
        f2h_kernel<<<(n4x + 255) / 256, 256>>>(x, x_ptr, n4x);
        const int n4w = N_QKV * D_ / 4;
        f2h_kernel<<<(n4w + 255) / 256, 256>>>(w_qkv, wqkv_ptr, n4w);
        const int n4o = D_ * D_ / 4;
        f2h_kernel<<<(n4o + 255) / 256, 256>>>(w_out, wout_ptr, n4o);
    }

    // 1) QKV projection with scatter epilogue
    {
        cudaFuncSetAttribute(mma_gemm_h<1>,
                             cudaFuncAttributeMaxDynamicSharedMemorySize, GEMM_SMEM);
        dim3 grid(N_QKV / 128, M_ / 128);
        mma_gemm_h<1><<<grid, 256, GEMM_SMEM>>>(x_ptr, wqkv_ptr, b_qkv, nullptr,
                                                N_QKV, D_);
    }

    // 2) Causal flash attention (fp16 mma + ldmatrix)
    {
        cudaFuncSetAttribute(attn_mma_h,
                             cudaFuncAttributeMaxDynamicSharedMemorySize, ATT_SMEM);
        dim3 grid(S_ / 128, B_ * H_);
        attn_mma_h<<<grid, 256, ATT_SMEM>>>(ctx_ptr);
    }

    // 3) Output projection
    {
        cudaFuncSetAttribute(mma_gemm_h<0>,
                             cudaFuncAttributeMaxDynamicSharedMemorySize, GEMM_SMEM);
        dim3 grid(D_ / 128, M_ / 128);
        mma_gemm_h<0><<<grid, 256, GEMM_SMEM>>>(ctx_ptr, wout_ptr, b_out, out,
                                                D_, D_);
    }
}